// round 7
// baseline (speedup 1.0000x reference)
#include <cuda_runtime.h>
#include <cuda_bf16.h>
#include <math.h>
#include <stdint.h>

#define NLAYER 2
#define BATCH  2
#define SEQ    2048
#define HID    1024
#define NHEAD  16
#define DHEAD  64
#define FFDIM  4096
#define NTOK   (BATCH*SEQ)      // 4096
#define QKVDIM (3*HID)          // 3072
#define KPAD   40               // GEMM: 32-elem K chunk padded to 40
#define KPQ    72               // flash: 64-elem rows padded to 72
#define KPV    136              // flash: 128-elem rows padded to 136

// ---------------- scratch (device globals) ----------------
__device__ __nv_bfloat16 g_h[NTOK*HID];
__device__ __nv_bfloat16 g_qkv[(size_t)NTOK*QKVDIM];
__device__ __nv_bfloat16 g_vt[(size_t)BATCH*NHEAD*DHEAD*SEQ];
__device__ __nv_bfloat16 g_ctx[NTOK*HID];
__device__ __nv_bfloat16 g_ff[(size_t)NTOK*FFDIM];
__device__ __nv_bfloat16 g_wq[(size_t)NLAYER*QKVDIM*HID];
__device__ __nv_bfloat16 g_wd[(size_t)NLAYER*HID*HID];
__device__ __nv_bfloat16 g_w1[(size_t)NLAYER*FFDIM*HID];
__device__ __nv_bfloat16 g_w2[(size_t)NLAYER*HID*FFDIM];

// ---------------- helpers ----------------
__device__ __forceinline__ uint32_t smem_u32(const void* p) {
    uint32_t a;
    asm("{ .reg .u64 t; cvta.to.shared.u64 t, %1; cvt.u32.u64 %0, t; }" : "=r"(a) : "l"(p));
    return a;
}
__device__ __forceinline__ void cp16(uint32_t s, const void* g) {
    asm volatile("cp.async.cg.shared.global [%0], [%1], 16;" :: "r"(s), "l"(g));
}
#define CP_COMMIT asm volatile("cp.async.commit_group;")
#define CP_WAIT1  asm volatile("cp.async.wait_group 1;")
#define CP_WAIT0  asm volatile("cp.async.wait_group 0;")

__device__ __forceinline__ void ldmx4(uint32_t* r, uint32_t addr) {
    asm volatile("ldmatrix.sync.aligned.m8n8.x4.shared.b16 {%0,%1,%2,%3}, [%4];"
                 : "=r"(r[0]), "=r"(r[1]), "=r"(r[2]), "=r"(r[3]) : "r"(addr));
}
__device__ __forceinline__ void mma16816(float* c, const uint32_t* a, const uint32_t* b) {
    asm volatile("mma.sync.aligned.m16n8k16.row.col.f32.bf16.bf16.f32 "
                 "{%0,%1,%2,%3}, {%4,%5,%6,%7}, {%8,%9}, {%0,%1,%2,%3};"
                 : "+f"(c[0]), "+f"(c[1]), "+f"(c[2]), "+f"(c[3])
                 : "r"(a[0]), "r"(a[1]), "r"(a[2]), "r"(a[3]), "r"(b[0]), "r"(b[1]));
}
__device__ __forceinline__ uint32_t pack_bf2(float a, float b) {
    __nv_bfloat162 h = __floats2bfloat162_rn(a, b);
    return *(uint32_t*)&h;
}
__device__ __forceinline__ float gelu_f(float v) {
    return 0.5f * v * (1.0f + erff(v * 0.70710678118654752440f));
}
__device__ __forceinline__ float warpSum(float v) {
#pragma unroll
    for (int o = 16; o > 0; o >>= 1) v += __shfl_xor_sync(0xffffffffu, v, o);
    return v;
}

// ---------------- LayerNorm (fp32 in, bf16 out) ----------------
__global__ __launch_bounds__(256)
void ln_kernel(const float* __restrict__ x, const float* __restrict__ w,
               const float* __restrict__ b, __nv_bfloat16* __restrict__ out)
{
    __shared__ float sh[8];
    __shared__ float stat;
    const int t = blockIdx.x;
    const float* xr = x + (size_t)t * HID;
    const int lane = threadIdx.x & 31, wp = threadIdx.x >> 5;

    float v[4];
    float s = 0.f;
#pragma unroll
    for (int i = 0; i < 4; i++) { v[i] = xr[threadIdx.x + i * 256]; s += v[i]; }
    s = warpSum(s);
    if (lane == 0) sh[wp] = s;
    __syncthreads();
    if (threadIdx.x == 0) {
        float r = 0.f;
#pragma unroll
        for (int i = 0; i < 8; i++) r += sh[i];
        stat = r * (1.0f / HID);
    }
    __syncthreads();
    const float mu = stat;

    float s2 = 0.f;
#pragma unroll
    for (int i = 0; i < 4; i++) { float d = v[i] - mu; s2 += d * d; }
    s2 = warpSum(s2);
    __syncthreads();
    if (lane == 0) sh[wp] = s2;
    __syncthreads();
    if (threadIdx.x == 0) {
        float r = 0.f;
#pragma unroll
        for (int i = 0; i < 8; i++) r += sh[i];
        stat = rsqrtf(r * (1.0f / HID) + 1e-5f);
    }
    __syncthreads();
    const float rs = stat;

    __nv_bfloat16* orow = out + (size_t)t * HID;
#pragma unroll
    for (int i = 0; i < 4; i++) {
        int c = threadIdx.x + i * 256;
        orow[c] = __float2bfloat16((v[i] - mu) * rs * w[c] + b[c]);
    }
}

// ---------------- merged weight convert fp32 -> bf16 (4 arrays via grid.y) ----------
__global__ __launch_bounds__(256)
void cvt4_kernel(const float* __restrict__ s0, __nv_bfloat16* __restrict__ d0, int n0,
                 const float* __restrict__ s1, __nv_bfloat16* __restrict__ d1, int n1,
                 const float* __restrict__ s2, __nv_bfloat16* __restrict__ d2, int n2,
                 const float* __restrict__ s3, __nv_bfloat16* __restrict__ d3, int n3)
{
    const float* src; __nv_bfloat16* dst; int n;
    switch (blockIdx.y) {
        case 0: src = s0; dst = d0; n = n0; break;
        case 1: src = s1; dst = d1; n = n1; break;
        case 2: src = s2; dst = d2; n = n2; break;
        default: src = s3; dst = d3; n = n3; break;
    }
    int i = blockIdx.x * 256 + threadIdx.x;
    if (i < n) {
        float4 v = ((const float4*)src)[i];
        uint2 o;
        o.x = pack_bf2(v.x, v.y);
        o.y = pack_bf2(v.z, v.w);
        ((uint2*)dst)[i] = o;
    }
}

// ---------------- V transpose: qkv v-part -> [B,NH,DH,S] ----------------
__global__ void vtrans_kernel(const __nv_bfloat16* __restrict__ qkv, __nv_bfloat16* __restrict__ vt)
{
    __shared__ __nv_bfloat16 t[32][33];
    const int z = blockIdx.z, b = z >> 4, h = z & 15;
    const int s0 = blockIdx.x * 32, d0 = blockIdx.y * 32;
    const int tx = threadIdx.x, ty = threadIdx.y;
    t[ty][tx] = qkv[(size_t)(b * SEQ + s0 + ty) * QKVDIM + 2 * HID + h * DHEAD + d0 + tx];
    __syncthreads();
    vt[(size_t)z * DHEAD * SEQ + (size_t)(d0 + ty) * SEQ + s0 + tx] = t[tx][ty];
}

// ---------------- flash attention: ctx = softmax(QK^T/8 + alibi, causal) V ----------
// grid (16 qtiles [reversed], B*NH). 8 warps, each owns 16 q-rows x full 128 k-tile.
__global__ __launch_bounds__(256)
void flash_kernel(const __nv_bfloat16* __restrict__ qkv,
                  const __nv_bfloat16* __restrict__ vt,
                  const float* __restrict__ alibi,
                  __nv_bfloat16* __restrict__ ctx)
{
    extern __shared__ __nv_bfloat16 sm[];
    const int tid = threadIdx.x, wid = tid >> 5, lane = tid & 31;
    const int qt = (int)gridDim.x - 1 - (int)blockIdx.x;   // big tiles first
    const int z = blockIdx.y, b = z >> 4, h = z & 15;

    const uint32_t qsa = smem_u32(sm);                              // Q: 128 x KPQ
    const uint32_t ksa[2] = { qsa + 128 * KPQ * 2, qsa + 2 * 128 * KPQ * 2 };
    const uint32_t vsa[2] = { qsa + 3 * 128 * KPQ * 2, qsa + 3 * 128 * KPQ * 2 + 64 * KPV * 2 };

    const __nv_bfloat16* Qg = qkv + ((size_t)(b * SEQ) + qt * 128) * QKVDIM + h * DHEAD;
    const __nv_bfloat16* Kg = qkv + (size_t)(b * SEQ) * QKVDIM + HID + h * DHEAD;
    const __nv_bfloat16* Vg = vt + (size_t)z * DHEAD * SEQ;
    const float slope = alibi[(size_t)z * SEQ + 1];   // alibi[...,c] == slope*c exactly

    {
#pragma unroll
        for (int it = 0; it < 4; it++) {
            int idx = tid + it * 256, row = idx >> 3, u = idx & 7;
            cp16(qsa + (uint32_t)(row * KPQ + u * 8) * 2, Qg + (size_t)row * QKVDIM + u * 8);
        }
#pragma unroll
        for (int it = 0; it < 4; it++) {
            int idx = tid + it * 256, row = idx >> 3, u = idx & 7;
            cp16(ksa[0] + (uint32_t)(row * KPQ + u * 8) * 2, Kg + (size_t)row * QKVDIM + u * 8);
        }
#pragma unroll
        for (int it = 0; it < 4; it++) {
            int idx = tid + it * 256, row = idx >> 4, u = idx & 15;
            cp16(vsa[0] + (uint32_t)(row * KPV + u * 8) * 2, Vg + (size_t)row * SEQ + u * 8);
        }
        CP_COMMIT;
    }
    CP_WAIT0;
    __syncthreads();

    uint32_t aQ[4][4];
#pragma unroll
    for (int kc = 0; kc < 4; kc++) {
        int row = wid * 16 + (lane & 7) + ((lane >> 3) & 1) * 8;
        int col = kc * 16 + ((lane >> 4) & 1) * 8;
        ldmx4(aQ[kc], qsa + (uint32_t)(row * KPQ + col) * 2);
    }

    float m0 = -1e30f, m1 = -1e30f, l0 = 0.f, l1 = 0.f;
    float oacc[8][4];
#pragma unroll
    for (int i = 0; i < 8; i++)
#pragma unroll
        for (int j = 0; j < 4; j++) oacc[i][j] = 0.f;

    const int rg0 = qt * 128 + wid * 16 + (lane >> 2);
    const int rg1 = rg0 + 8;

    for (int kt = 0; kt <= qt; kt++) {
        const int cur = kt & 1;
        if (kt < qt) {
            const __nv_bfloat16* Kn = Kg + (size_t)(kt + 1) * 128 * QKVDIM;
            const __nv_bfloat16* Vn = Vg + (kt + 1) * 128;
#pragma unroll
            for (int it = 0; it < 4; it++) {
                int idx = tid + it * 256, row = idx >> 3, u = idx & 7;
                cp16(ksa[cur ^ 1] + (uint32_t)(row * KPQ + u * 8) * 2, Kn + (size_t)row * QKVDIM + u * 8);
            }
#pragma unroll
            for (int it = 0; it < 4; it++) {
                int idx = tid + it * 256, row = idx >> 4, u = idx & 15;
                cp16(vsa[cur ^ 1] + (uint32_t)(row * KPV + u * 8) * 2, Vn + (size_t)row * SEQ + u * 8);
            }
            CP_COMMIT;
        }

        float sacc[16][4];
#pragma unroll
        for (int i = 0; i < 16; i++)
#pragma unroll
            for (int j = 0; j < 4; j++) sacc[i][j] = 0.f;
#pragma unroll
        for (int kc = 0; kc < 4; kc++) {
#pragma unroll
            for (int nb = 0; nb < 8; nb++) {
                uint32_t r[4];
                int row = nb * 16 + (lane & 7) + ((lane >> 4) & 1) * 8;
                int col = kc * 16 + ((lane >> 3) & 1) * 8;
                ldmx4(r, ksa[cur] + (uint32_t)(row * KPQ + col) * 2);
                mma16816(sacc[2 * nb], aQ[kc], r);
                mma16816(sacc[2 * nb + 1], aQ[kc], r + 2);
            }
        }

        float mx0 = -1e30f, mx1 = -1e30f;
        const int cb = kt * 128 + (lane & 3) * 2;
#pragma unroll
        for (int nt = 0; nt < 16; nt++) {
            int c0 = cb + nt * 8, c1 = c0 + 1;
            float a0 = slope * (float)c0, a1 = slope * (float)c1;
            float s0 = (c0 <= rg0) ? fmaf(sacc[nt][0], 0.125f, a0) : -1e30f;
            float s1 = (c1 <= rg0) ? fmaf(sacc[nt][1], 0.125f, a1) : -1e30f;
            float s2 = (c0 <= rg1) ? fmaf(sacc[nt][2], 0.125f, a0) : -1e30f;
            float s3 = (c1 <= rg1) ? fmaf(sacc[nt][3], 0.125f, a1) : -1e30f;
            sacc[nt][0] = s0; sacc[nt][1] = s1; sacc[nt][2] = s2; sacc[nt][3] = s3;
            mx0 = fmaxf(mx0, fmaxf(s0, s1)); mx1 = fmaxf(mx1, fmaxf(s2, s3));
        }
        mx0 = fmaxf(mx0, __shfl_xor_sync(0xffffffffu, mx0, 1));
        mx0 = fmaxf(mx0, __shfl_xor_sync(0xffffffffu, mx0, 2));
        mx1 = fmaxf(mx1, __shfl_xor_sync(0xffffffffu, mx1, 1));
        mx1 = fmaxf(mx1, __shfl_xor_sync(0xffffffffu, mx1, 2));

        const float mn0 = fmaxf(m0, mx0), mn1 = fmaxf(m1, mx1);
        const float sc0 = __expf(m0 - mn0), sc1 = __expf(m1 - mn1);
        float rs0 = 0.f, rs1 = 0.f;
#pragma unroll
        for (int nt = 0; nt < 16; nt++) {
            float p0 = __expf(sacc[nt][0] - mn0), p1 = __expf(sacc[nt][1] - mn0);
            float p2 = __expf(sacc[nt][2] - mn1), p3 = __expf(sacc[nt][3] - mn1);
            sacc[nt][0] = p0; sacc[nt][1] = p1; sacc[nt][2] = p2; sacc[nt][3] = p3;
            rs0 += p0 + p1; rs1 += p2 + p3;
        }
        rs0 += __shfl_xor_sync(0xffffffffu, rs0, 1);
        rs0 += __shfl_xor_sync(0xffffffffu, rs0, 2);
        rs1 += __shfl_xor_sync(0xffffffffu, rs1, 1);
        rs1 += __shfl_xor_sync(0xffffffffu, rs1, 2);
        l0 = l0 * sc0 + rs0; l1 = l1 * sc1 + rs1;
        m0 = mn0; m1 = mn1;
#pragma unroll
        for (int nt = 0; nt < 8; nt++) {
            oacc[nt][0] *= sc0; oacc[nt][1] *= sc0;
            oacc[nt][2] *= sc1; oacc[nt][3] *= sc1;
        }

#pragma unroll
        for (int kc2 = 0; kc2 < 8; kc2++) {
            uint32_t pa[4] = {
                pack_bf2(sacc[2 * kc2][0],     sacc[2 * kc2][1]),
                pack_bf2(sacc[2 * kc2][2],     sacc[2 * kc2][3]),
                pack_bf2(sacc[2 * kc2 + 1][0], sacc[2 * kc2 + 1][1]),
                pack_bf2(sacc[2 * kc2 + 1][2], sacc[2 * kc2 + 1][3]) };
#pragma unroll
            for (int nb = 0; nb < 4; nb++) {
                uint32_t r[4];
                int row = nb * 16 + (lane & 7) + ((lane >> 4) & 1) * 8;
                int col = kc2 * 16 + ((lane >> 3) & 1) * 8;
                ldmx4(r, vsa[cur] + (uint32_t)(row * KPV + col) * 2);
                mma16816(oacc[2 * nb], pa, r);
                mma16816(oacc[2 * nb + 1], pa, r + 2);
            }
        }

        if (kt < qt) CP_WAIT0;
        __syncthreads();
    }

    const float inv0 = 1.0f / l0, inv1 = 1.0f / l1;
    const int tok0 = b * SEQ + qt * 128 + wid * 16 + (lane >> 2);
#pragma unroll
    for (int nt = 0; nt < 8; nt++) {
        int c = h * DHEAD + nt * 8 + (lane & 3) * 2;
        *(uint32_t*)(ctx + (size_t)tok0 * HID + c) = pack_bf2(oacc[nt][0] * inv0, oacc[nt][1] * inv0);
        *(uint32_t*)(ctx + (size_t)(tok0 + 8) * HID + c) = pack_bf2(oacc[nt][2] * inv1, oacc[nt][3] * inv1);
    }
}

// ---------------- bf16 NT GEMM: 128 threads, warp tile 64x64, 3-stage ----------------
// EPI: 0 = bias -> bf16, 1 = bias+gelu -> bf16, 2 = bias+residual -> fp32
#define STG_B (128 * KPAD * 2)   // bytes per stage per operand (10240)

// 128 threads: thread tid loads row tid (32 elems = 4 cp16)
__device__ __forceinline__ void cp_row(uint32_t sbase, const __nv_bfloat16* g, int ld, int tid) {
    const __nv_bfloat16* src = g + (size_t)tid * ld;
    uint32_t d = sbase + (uint32_t)(tid * KPAD) * 2;
#pragma unroll
    for (int q = 0; q < 4; q++)
        cp16(d + q * 16, src + q * 8);
}

template<int EPI>
__global__ __launch_bounds__(128, 2)
void mm_gemm(const __nv_bfloat16* __restrict__ A, int lda,
             const __nv_bfloat16* __restrict__ B, int ldb,
             const float* __restrict__ bias, const float* __restrict__ res,
             void* __restrict__ Cout, int ldc, int K)
{
    extern __shared__ __nv_bfloat16 smbuf[];
    const uint32_t as0 = smem_u32(smbuf);
    const uint32_t bs0 = as0 + 3 * STG_B;
    const int tid = threadIdx.x, wid = tid >> 5, lane = tid & 31;
    const int wm = wid & 1, wn = wid >> 1;
    const int rowB = blockIdx.y * 128, colB = blockIdx.x * 128;
    const __nv_bfloat16* Ag = A + (size_t)rowB * lda;
    const __nv_bfloat16* Bg = B + (size_t)colB * ldb;

    float acc[4][8][4];
#pragma unroll
    for (int i = 0; i < 4; i++)
#pragma unroll
        for (int j = 0; j < 8; j++)
#pragma unroll
            for (int k = 0; k < 4; k++) acc[i][j][k] = 0.f;

    const int NCH = K >> 5;
    cp_row(as0, Ag, lda, tid); cp_row(bs0, Bg, ldb, tid); CP_COMMIT;
    cp_row(as0 + STG_B, Ag + 32, lda, tid); cp_row(bs0 + STG_B, Bg + 32, ldb, tid); CP_COMMIT;

    for (int kc = 0; kc < NCH; kc++) {
        if (kc == NCH - 1) { CP_WAIT0; } else { CP_WAIT1; }
        __syncthreads();
        if (kc + 2 < NCH) {
            int st = (kc + 2) % 3;
            cp_row(as0 + st * STG_B, Ag + (kc + 2) * 32, lda, tid);
            cp_row(bs0 + st * STG_B, Bg + (kc + 2) * 32, ldb, tid);
            CP_COMMIT;
        }
        const int st = kc % 3;
        const uint32_t abase = as0 + st * STG_B, bbase = bs0 + st * STG_B;
#pragma unroll
        for (int ks = 0; ks < 32; ks += 16) {
            uint32_t a[4][4];
#pragma unroll
            for (int mt = 0; mt < 4; mt++) {
                int row = wm * 64 + mt * 16 + (lane & 7) + ((lane >> 3) & 1) * 8;
                int col = ks + ((lane >> 4) & 1) * 8;
                ldmx4(a[mt], abase + (uint32_t)(row * KPAD + col) * 2);
            }
            uint32_t bf[8][2];
#pragma unroll
            for (int nb = 0; nb < 4; nb++) {
                int row = wn * 64 + nb * 16 + (lane & 7) + ((lane >> 4) & 1) * 8;
                int col = ks + ((lane >> 3) & 1) * 8;
                uint32_t r[4];
                ldmx4(r, bbase + (uint32_t)(row * KPAD + col) * 2);
                bf[2 * nb][0] = r[0]; bf[2 * nb][1] = r[1];
                bf[2 * nb + 1][0] = r[2]; bf[2 * nb + 1][1] = r[3];
            }
#pragma unroll
            for (int mt = 0; mt < 4; mt++)
#pragma unroll
                for (int nt = 0; nt < 8; nt++)
                    mma16816(acc[mt][nt], a[mt], bf[nt]);
        }
    }

#pragma unroll
    for (int mt = 0; mt < 4; mt++) {
#pragma unroll
        for (int nt = 0; nt < 8; nt++) {
            const float* ac = acc[mt][nt];
            const int r0 = rowB + wm * 64 + mt * 16 + (lane >> 2);
            const int c = colB + wn * 64 + nt * 8 + (lane & 3) * 2;
            const float b0 = bias[c], b1 = bias[c + 1];
            if (EPI == 2) {
                float* C = (float*)Cout;
                float2 ra = *(const float2*)(res + (size_t)r0 * ldc + c);
                float2 rb = *(const float2*)(res + (size_t)(r0 + 8) * ldc + c);
                float2 o0 = { ac[0] + b0 + ra.x, ac[1] + b1 + ra.y };
                float2 o1 = { ac[2] + b0 + rb.x, ac[3] + b1 + rb.y };
                *(float2*)(C + (size_t)r0 * ldc + c) = o0;
                *(float2*)(C + (size_t)(r0 + 8) * ldc + c) = o1;
            } else {
                __nv_bfloat16* C = (__nv_bfloat16*)Cout;
                float v0 = ac[0] + b0, v1 = ac[1] + b1;
                float v2 = ac[2] + b0, v3 = ac[3] + b1;
                if (EPI == 1) { v0 = gelu_f(v0); v1 = gelu_f(v1); v2 = gelu_f(v2); v3 = gelu_f(v3); }
                *(uint32_t*)(C + (size_t)r0 * ldc + c) = pack_bf2(v0, v1);
                *(uint32_t*)(C + (size_t)(r0 + 8) * ldc + c) = pack_bf2(v2, v3);
            }
        }
    }
}

// ---------------- launch ----------------
extern "C" void kernel_launch(void* const* d_in, const int* in_sizes, int n_in,
                              void* d_out, int out_size)
{
    (void)in_sizes; (void)n_in; (void)out_size;
    const float* hidden  = (const float*)d_in[0];
    const float* alibi   = (const float*)d_in[1];
    const float* qkv_w   = (const float*)d_in[2];
    const float* qkv_b   = (const float*)d_in[3];
    const float* dense_w = (const float*)d_in[4];
    const float* dense_b = (const float*)d_in[5];
    const float* w1      = (const float*)d_in[6];
    const float* b1      = (const float*)d_in[7];
    const float* w2      = (const float*)d_in[8];
    const float* b2      = (const float*)d_in[9];
    const float* ln1w    = (const float*)d_in[10];
    const float* ln1b    = (const float*)d_in[11];
    const float* ln2w    = (const float*)d_in[12];
    const float* ln2b    = (const float*)d_in[13];
    float* x = (float*)d_out;

    __nv_bfloat16 *ph, *pqkv, *pvt, *pctx, *pff, *pwq, *pwd, *pw1, *pw2;
    cudaGetSymbolAddress((void**)&ph,   g_h);
    cudaGetSymbolAddress((void**)&pqkv, g_qkv);
    cudaGetSymbolAddress((void**)&pvt,  g_vt);
    cudaGetSymbolAddress((void**)&pctx, g_ctx);
    cudaGetSymbolAddress((void**)&pff,  g_ff);
    cudaGetSymbolAddress((void**)&pwq,  g_wq);
    cudaGetSymbolAddress((void**)&pwd,  g_wd);
    cudaGetSymbolAddress((void**)&pw1,  g_w1);
    cudaGetSymbolAddress((void**)&pw2,  g_w2);

    const int GEMM_SMEM  = 6 * STG_B;                                  // 61440
    const int FLASH_SMEM = (3 * 128 * KPQ + 2 * 64 * KPV) * 2;         // 90112
    cudaFuncSetAttribute(mm_gemm<0>, cudaFuncAttributeMaxDynamicSharedMemorySize, GEMM_SMEM);
    cudaFuncSetAttribute(mm_gemm<1>, cudaFuncAttributeMaxDynamicSharedMemorySize, GEMM_SMEM);
    cudaFuncSetAttribute(mm_gemm<2>, cudaFuncAttributeMaxDynamicSharedMemorySize, GEMM_SMEM);
    cudaFuncSetAttribute(flash_kernel, cudaFuncAttributeMaxDynamicSharedMemorySize, FLASH_SMEM);

    cudaMemcpyAsync(x, hidden, sizeof(float) * (size_t)NTOK * HID, cudaMemcpyDeviceToDevice);

    // weights -> bf16 (all 4 arrays in one launch)
    const int nq = NLAYER * QKVDIM * HID / 4, nd = NLAYER * HID * HID / 4;
    const int n1 = NLAYER * FFDIM * HID / 4, n2 = NLAYER * HID * FFDIM / 4;
    int nmax = n1 > nq ? n1 : nq;
    cvt4_kernel<<<dim3((nmax + 255) / 256, 4), 256>>>(
        qkv_w, pwq, nq, dense_w, pwd, nd, w1, pw1, n1, w2, pw2, n2);

    for (int l = 0; l < NLAYER; l++) {
        // --- attention ---
        ln_kernel<<<NTOK, 256>>>(x, ln1w + l * HID, ln1b + l * HID, ph);
        mm_gemm<0><<<dim3(QKVDIM / 128, NTOK / 128), 128, GEMM_SMEM>>>(
            ph, HID, pwq + (size_t)l * QKVDIM * HID, HID,
            qkv_b + (size_t)l * QKVDIM, nullptr, pqkv, QKVDIM, HID);
        vtrans_kernel<<<dim3(SEQ / 32, DHEAD / 32, BATCH * NHEAD), dim3(32, 32)>>>(pqkv, pvt);
        flash_kernel<<<dim3(SEQ / 128, BATCH * NHEAD), 256, FLASH_SMEM>>>(pqkv, pvt, alibi, pctx);
        mm_gemm<2><<<dim3(HID / 128, NTOK / 128), 128, GEMM_SMEM>>>(
            pctx, HID, pwd + (size_t)l * HID * HID, HID,
            dense_b + (size_t)l * HID, x, x, HID, HID);
        // --- MLP ---
        ln_kernel<<<NTOK, 256>>>(x, ln2w + l * HID, ln2b + l * HID, ph);
        mm_gemm<1><<<dim3(FFDIM / 128, NTOK / 128), 128, GEMM_SMEM>>>(
            ph, HID, pw1 + (size_t)l * FFDIM * HID, HID,
            b1 + (size_t)l * FFDIM, nullptr, pff, FFDIM, HID);
        mm_gemm<2><<<dim3(HID / 128, NTOK / 128), 128, GEMM_SMEM>>>(
            pff, FFDIM, pw2 + (size_t)l * HID * FFDIM, FFDIM,
            b2 + (size_t)l * HID, x, x, HID, FFDIM);
    }
}

// round 9
// speedup vs baseline: 1.0886x; 1.0886x over previous
#include <cuda_runtime.h>
#include <cuda_bf16.h>
#include <math.h>
#include <stdint.h>

#define NLAYER 2
#define BATCH  2
#define SEQ    2048
#define HID    1024
#define NHEAD  16
#define DHEAD  64
#define FFDIM  4096
#define NTOK   (BATCH*SEQ)      // 4096
#define QKVDIM (3*HID)          // 3072
#define KPG    72               // GEMM: 64-elem K chunk padded to 72 elems
#define KPQ    72               // flash: 64-elem rows padded to 72
#define KPV    136              // flash: 128-elem rows padded to 136

// ---------------- scratch (device globals) ----------------
__device__ __nv_bfloat16 g_h[NTOK*HID];
__device__ __nv_bfloat16 g_qkv[(size_t)NTOK*QKVDIM];
__device__ __nv_bfloat16 g_vt[(size_t)BATCH*NHEAD*DHEAD*SEQ];
__device__ __nv_bfloat16 g_ctx[NTOK*HID];
__device__ __nv_bfloat16 g_ff[(size_t)NTOK*FFDIM];
__device__ __nv_bfloat16 g_wq[(size_t)NLAYER*QKVDIM*HID];
__device__ __nv_bfloat16 g_wd[(size_t)NLAYER*HID*HID];
__device__ __nv_bfloat16 g_w1[(size_t)NLAYER*FFDIM*HID];
__device__ __nv_bfloat16 g_w2[(size_t)NLAYER*HID*FFDIM];

// ---------------- helpers ----------------
__device__ __forceinline__ uint32_t smem_u32(const void* p) {
    uint32_t a;
    asm("{ .reg .u64 t; cvta.to.shared.u64 t, %1; cvt.u32.u64 %0, t; }" : "=r"(a) : "l"(p));
    return a;
}
__device__ __forceinline__ void cp16(uint32_t s, const void* g) {
    asm volatile("cp.async.cg.shared.global [%0], [%1], 16;" :: "r"(s), "l"(g));
}
#define CP_COMMIT asm volatile("cp.async.commit_group;")
#define CP_WAIT1  asm volatile("cp.async.wait_group 1;")
#define CP_WAIT0  asm volatile("cp.async.wait_group 0;")

__device__ __forceinline__ void ldmx4(uint32_t* r, uint32_t addr) {
    asm volatile("ldmatrix.sync.aligned.m8n8.x4.shared.b16 {%0,%1,%2,%3}, [%4];"
                 : "=r"(r[0]), "=r"(r[1]), "=r"(r[2]), "=r"(r[3]) : "r"(addr));
}
__device__ __forceinline__ void mma16816(float* c, const uint32_t* a, const uint32_t* b) {
    asm volatile("mma.sync.aligned.m16n8k16.row.col.f32.bf16.bf16.f32 "
                 "{%0,%1,%2,%3}, {%4,%5,%6,%7}, {%8,%9}, {%0,%1,%2,%3};"
                 : "+f"(c[0]), "+f"(c[1]), "+f"(c[2]), "+f"(c[3])
                 : "r"(a[0]), "r"(a[1]), "r"(a[2]), "r"(a[3]), "r"(b[0]), "r"(b[1]));
}
__device__ __forceinline__ uint32_t pack_bf2(float a, float b) {
    __nv_bfloat162 h = __floats2bfloat162_rn(a, b);
    return *(uint32_t*)&h;
}
__device__ __forceinline__ float gelu_f(float v) {
    return 0.5f * v * (1.0f + erff(v * 0.70710678118654752440f));
}
__device__ __forceinline__ float warpSum(float v) {
#pragma unroll
    for (int o = 16; o > 0; o >>= 1) v += __shfl_xor_sync(0xffffffffu, v, o);
    return v;
}

// ---------------- LayerNorm (fp32 in, bf16 out) ----------------
__global__ __launch_bounds__(256)
void ln_kernel(const float* __restrict__ x, const float* __restrict__ w,
               const float* __restrict__ b, __nv_bfloat16* __restrict__ out)
{
    __shared__ float sh[8];
    __shared__ float stat;
    const int t = blockIdx.x;
    const float* xr = x + (size_t)t * HID;
    const int lane = threadIdx.x & 31, wp = threadIdx.x >> 5;

    float v[4];
    float s = 0.f;
#pragma unroll
    for (int i = 0; i < 4; i++) { v[i] = xr[threadIdx.x + i * 256]; s += v[i]; }
    s = warpSum(s);
    if (lane == 0) sh[wp] = s;
    __syncthreads();
    if (threadIdx.x == 0) {
        float r = 0.f;
#pragma unroll
        for (int i = 0; i < 8; i++) r += sh[i];
        stat = r * (1.0f / HID);
    }
    __syncthreads();
    const float mu = stat;

    float s2 = 0.f;
#pragma unroll
    for (int i = 0; i < 4; i++) { float d = v[i] - mu; s2 += d * d; }
    s2 = warpSum(s2);
    __syncthreads();
    if (lane == 0) sh[wp] = s2;
    __syncthreads();
    if (threadIdx.x == 0) {
        float r = 0.f;
#pragma unroll
        for (int i = 0; i < 8; i++) r += sh[i];
        stat = rsqrtf(r * (1.0f / HID) + 1e-5f);
    }
    __syncthreads();
    const float rs = stat;

    __nv_bfloat16* orow = out + (size_t)t * HID;
#pragma unroll
    for (int i = 0; i < 4; i++) {
        int c = threadIdx.x + i * 256;
        orow[c] = __float2bfloat16((v[i] - mu) * rs * w[c] + b[c]);
    }
}

// ---------------- merged weight convert fp32 -> bf16 (4 arrays via grid.y) ----------
__global__ __launch_bounds__(256)
void cvt4_kernel(const float* __restrict__ s0, __nv_bfloat16* __restrict__ d0, int n0,
                 const float* __restrict__ s1, __nv_bfloat16* __restrict__ d1, int n1,
                 const float* __restrict__ s2, __nv_bfloat16* __restrict__ d2, int n2,
                 const float* __restrict__ s3, __nv_bfloat16* __restrict__ d3, int n3)
{
    const float* src; __nv_bfloat16* dst; int n;
    switch (blockIdx.y) {
        case 0: src = s0; dst = d0; n = n0; break;
        case 1: src = s1; dst = d1; n = n1; break;
        case 2: src = s2; dst = d2; n = n2; break;
        default: src = s3; dst = d3; n = n3; break;
    }
    int i = blockIdx.x * 256 + threadIdx.x;
    if (i < n) {
        float4 v = ((const float4*)src)[i];
        uint2 o;
        o.x = pack_bf2(v.x, v.y);
        o.y = pack_bf2(v.z, v.w);
        ((uint2*)dst)[i] = o;
    }
}

// ---------------- V transpose: 64x64 tiles, vectorized (FIXED load coverage) --------
// grid (SEQ/64, 1, B*NH), 256 threads
__global__ __launch_bounds__(256)
void vtrans_kernel(const __nv_bfloat16* __restrict__ qkv, __nv_bfloat16* __restrict__ vt)
{
    __shared__ __nv_bfloat16 t[64 * KPQ];
    const int z = blockIdx.z, b = z >> 4, h = z & 15;
    const int s0 = blockIdx.x * 64;
    const int tid = threadIdx.x;
    // load: 64 s-rows x 64 d-cols, 8 elems/thread/iter, 2 iters (512 uint4 total)
#pragma unroll
    for (int it = 0; it < 2; it++) {
        int idx = tid + it * 256;
        int srow = idx >> 3, d8 = (idx & 7) * 8;
        const __nv_bfloat16* src = qkv + (size_t)(b * SEQ + s0 + srow) * QKVDIM + 2 * HID + h * DHEAD + d8;
        *(uint4*)&t[srow * KPQ + d8] = *(const uint4*)src;
    }
    __syncthreads();
    // store transposed: thread handles d-rows (tid>>3) and (tid>>3)+32, s-cols (tid&7)*8..+7
#pragma unroll
    for (int half = 0; half < 2; half++) {
        int drow = (tid >> 3) + half * 32, s8 = (tid & 7) * 8;
        __nv_bfloat16 vbuf[8];
#pragma unroll
        for (int i = 0; i < 8; i++) vbuf[i] = t[(s8 + i) * KPQ + drow];
        *(uint4*)(vt + (size_t)z * DHEAD * SEQ + (size_t)drow * SEQ + s0 + s8) = *(uint4*)vbuf;
    }
}

// ---------------- flash attention: ctx = softmax(QK^T/8 + alibi, causal) V ----------
// grid (16 qtiles [reversed], B*NH). 8 warps, each owns 16 q-rows x full 128 k-tile.
__global__ __launch_bounds__(256)
void flash_kernel(const __nv_bfloat16* __restrict__ qkv,
                  const __nv_bfloat16* __restrict__ vt,
                  const float* __restrict__ alibi,
                  __nv_bfloat16* __restrict__ ctx)
{
    extern __shared__ __nv_bfloat16 sm[];
    const int tid = threadIdx.x, wid = tid >> 5, lane = tid & 31;
    const int qt = (int)gridDim.x - 1 - (int)blockIdx.x;   // big tiles first
    const int z = blockIdx.y, b = z >> 4, h = z & 15;

    const uint32_t qsa = smem_u32(sm);                              // Q: 128 x KPQ
    const uint32_t ksa[2] = { qsa + 128 * KPQ * 2, qsa + 2 * 128 * KPQ * 2 };
    const uint32_t vsa[2] = { qsa + 3 * 128 * KPQ * 2, qsa + 3 * 128 * KPQ * 2 + 64 * KPV * 2 };

    const __nv_bfloat16* Qg = qkv + ((size_t)(b * SEQ) + qt * 128) * QKVDIM + h * DHEAD;
    const __nv_bfloat16* Kg = qkv + (size_t)(b * SEQ) * QKVDIM + HID + h * DHEAD;
    const __nv_bfloat16* Vg = vt + (size_t)z * DHEAD * SEQ;
    const float slope = alibi[(size_t)z * SEQ + 1];   // alibi[...,c] == slope*c exactly

    {
#pragma unroll
        for (int it = 0; it < 4; it++) {
            int idx = tid + it * 256, row = idx >> 3, u = idx & 7;
            cp16(qsa + (uint32_t)(row * KPQ + u * 8) * 2, Qg + (size_t)row * QKVDIM + u * 8);
        }
#pragma unroll
        for (int it = 0; it < 4; it++) {
            int idx = tid + it * 256, row = idx >> 3, u = idx & 7;
            cp16(ksa[0] + (uint32_t)(row * KPQ + u * 8) * 2, Kg + (size_t)row * QKVDIM + u * 8);
        }
#pragma unroll
        for (int it = 0; it < 4; it++) {
            int idx = tid + it * 256, row = idx >> 4, u = idx & 15;
            cp16(vsa[0] + (uint32_t)(row * KPV + u * 8) * 2, Vg + (size_t)row * SEQ + u * 8);
        }
        CP_COMMIT;
    }
    CP_WAIT0;
    __syncthreads();

    uint32_t aQ[4][4];
#pragma unroll
    for (int kc = 0; kc < 4; kc++) {
        int row = wid * 16 + (lane & 7) + ((lane >> 3) & 1) * 8;
        int col = kc * 16 + ((lane >> 4) & 1) * 8;
        ldmx4(aQ[kc], qsa + (uint32_t)(row * KPQ + col) * 2);
    }

    float m0 = -1e30f, m1 = -1e30f, l0 = 0.f, l1 = 0.f;
    float oacc[8][4];
#pragma unroll
    for (int i = 0; i < 8; i++)
#pragma unroll
        for (int j = 0; j < 4; j++) oacc[i][j] = 0.f;

    const int rg0 = qt * 128 + wid * 16 + (lane >> 2);
    const int rg1 = rg0 + 8;

    for (int kt = 0; kt <= qt; kt++) {
        const int cur = kt & 1;
        if (kt < qt) {
            const __nv_bfloat16* Kn = Kg + (size_t)(kt + 1) * 128 * QKVDIM;
            const __nv_bfloat16* Vn = Vg + (kt + 1) * 128;
#pragma unroll
            for (int it = 0; it < 4; it++) {
                int idx = tid + it * 256, row = idx >> 3, u = idx & 7;
                cp16(ksa[cur ^ 1] + (uint32_t)(row * KPQ + u * 8) * 2, Kn + (size_t)row * QKVDIM + u * 8);
            }
#pragma unroll
            for (int it = 0; it < 4; it++) {
                int idx = tid + it * 256, row = idx >> 4, u = idx & 15;
                cp16(vsa[cur ^ 1] + (uint32_t)(row * KPV + u * 8) * 2, Vn + (size_t)row * SEQ + u * 8);
            }
            CP_COMMIT;
        }

        float sacc[16][4];
#pragma unroll
        for (int i = 0; i < 16; i++)
#pragma unroll
            for (int j = 0; j < 4; j++) sacc[i][j] = 0.f;
#pragma unroll
        for (int kc = 0; kc < 4; kc++) {
#pragma unroll
            for (int nb = 0; nb < 8; nb++) {
                uint32_t r[4];
                int row = nb * 16 + (lane & 7) + ((lane >> 4) & 1) * 8;
                int col = kc * 16 + ((lane >> 3) & 1) * 8;
                ldmx4(r, ksa[cur] + (uint32_t)(row * KPQ + col) * 2);
                mma16816(sacc[2 * nb], aQ[kc], r);
                mma16816(sacc[2 * nb + 1], aQ[kc], r + 2);
            }
        }

        float mx0 = -1e30f, mx1 = -1e30f;
        const int cb = kt * 128 + (lane & 3) * 2;
#pragma unroll
        for (int nt = 0; nt < 16; nt++) {
            int c0 = cb + nt * 8, c1 = c0 + 1;
            float a0 = slope * (float)c0, a1 = slope * (float)c1;
            float s0 = (c0 <= rg0) ? fmaf(sacc[nt][0], 0.125f, a0) : -1e30f;
            float s1 = (c1 <= rg0) ? fmaf(sacc[nt][1], 0.125f, a1) : -1e30f;
            float s2 = (c0 <= rg1) ? fmaf(sacc[nt][2], 0.125f, a0) : -1e30f;
            float s3 = (c1 <= rg1) ? fmaf(sacc[nt][3], 0.125f, a1) : -1e30f;
            sacc[nt][0] = s0; sacc[nt][1] = s1; sacc[nt][2] = s2; sacc[nt][3] = s3;
            mx0 = fmaxf(mx0, fmaxf(s0, s1)); mx1 = fmaxf(mx1, fmaxf(s2, s3));
        }
        mx0 = fmaxf(mx0, __shfl_xor_sync(0xffffffffu, mx0, 1));
        mx0 = fmaxf(mx0, __shfl_xor_sync(0xffffffffu, mx0, 2));
        mx1 = fmaxf(mx1, __shfl_xor_sync(0xffffffffu, mx1, 1));
        mx1 = fmaxf(mx1, __shfl_xor_sync(0xffffffffu, mx1, 2));

        const float mn0 = fmaxf(m0, mx0), mn1 = fmaxf(m1, mx1);
        const float sc0 = __expf(m0 - mn0), sc1 = __expf(m1 - mn1);
        float rs0 = 0.f, rs1 = 0.f;
#pragma unroll
        for (int nt = 0; nt < 16; nt++) {
            float p0 = __expf(sacc[nt][0] - mn0), p1 = __expf(sacc[nt][1] - mn0);
            float p2 = __expf(sacc[nt][2] - mn1), p3 = __expf(sacc[nt][3] - mn1);
            sacc[nt][0] = p0; sacc[nt][1] = p1; sacc[nt][2] = p2; sacc[nt][3] = p3;
            rs0 += p0 + p1; rs1 += p2 + p3;
        }
        rs0 += __shfl_xor_sync(0xffffffffu, rs0, 1);
        rs0 += __shfl_xor_sync(0xffffffffu, rs0, 2);
        rs1 += __shfl_xor_sync(0xffffffffu, rs1, 1);
        rs1 += __shfl_xor_sync(0xffffffffu, rs1, 2);
        l0 = l0 * sc0 + rs0; l1 = l1 * sc1 + rs1;
        m0 = mn0; m1 = mn1;
#pragma unroll
        for (int nt = 0; nt < 8; nt++) {
            oacc[nt][0] *= sc0; oacc[nt][1] *= sc0;
            oacc[nt][2] *= sc1; oacc[nt][3] *= sc1;
        }

#pragma unroll
        for (int kc2 = 0; kc2 < 8; kc2++) {
            uint32_t pa[4] = {
                pack_bf2(sacc[2 * kc2][0],     sacc[2 * kc2][1]),
                pack_bf2(sacc[2 * kc2][2],     sacc[2 * kc2][3]),
                pack_bf2(sacc[2 * kc2 + 1][0], sacc[2 * kc2 + 1][1]),
                pack_bf2(sacc[2 * kc2 + 1][2], sacc[2 * kc2 + 1][3]) };
#pragma unroll
            for (int nb = 0; nb < 4; nb++) {
                uint32_t r[4];
                int row = nb * 16 + (lane & 7) + ((lane >> 4) & 1) * 8;
                int col = kc2 * 16 + ((lane >> 3) & 1) * 8;
                ldmx4(r, vsa[cur] + (uint32_t)(row * KPV + col) * 2);
                mma16816(oacc[2 * nb], pa, r);
                mma16816(oacc[2 * nb + 1], pa, r + 2);
            }
        }

        if (kt < qt) CP_WAIT0;
        __syncthreads();
    }

    const float inv0 = 1.0f / l0, inv1 = 1.0f / l1;
    const int tok0 = b * SEQ + qt * 128 + wid * 16 + (lane >> 2);
#pragma unroll
    for (int nt = 0; nt < 8; nt++) {
        int c = h * DHEAD + nt * 8 + (lane & 3) * 2;
        *(uint32_t*)(ctx + (size_t)tok0 * HID + c) = pack_bf2(oacc[nt][0] * inv0, oacc[nt][1] * inv0);
        *(uint32_t*)(ctx + (size_t)(tok0 + 8) * HID + c) = pack_bf2(oacc[nt][2] * inv1, oacc[nt][3] * inv1);
    }
}

// ---------------- bf16 NT GEMM: 256 threads, warp tile 32x64, K-chunk 64, 3-stage ----
// EPI: 0 = bias -> bf16, 1 = bias+gelu -> bf16, 2 = bias+residual -> fp32
#define STG_B (128 * KPG * 2)   // bytes per stage per operand (18432)

// 256 threads: thread handles (row = tid>>1, half = tid&1), 4 cp16 = 64B
__device__ __forceinline__ void cp_chunk64(uint32_t sbase, const __nv_bfloat16* g, int ld, int tid) {
    const int row = tid >> 1, half = tid & 1;
    const __nv_bfloat16* src = g + (size_t)row * ld + half * 32;
    uint32_t d = sbase + (uint32_t)(row * KPG + half * 32) * 2;
#pragma unroll
    for (int q = 0; q < 4; q++)
        cp16(d + q * 16, src + q * 8);
}

template<int EPI>
__global__ __launch_bounds__(256, 2)
void mm_gemm(const __nv_bfloat16* __restrict__ A, int lda,
             const __nv_bfloat16* __restrict__ B, int ldb,
             const float* __restrict__ bias, const float* __restrict__ res,
             void* __restrict__ Cout, int ldc, int K)
{
    extern __shared__ __nv_bfloat16 smbuf[];
    const uint32_t as0 = smem_u32(smbuf);
    const uint32_t bs0 = as0 + 3 * STG_B;
    const int tid = threadIdx.x, wid = tid >> 5, lane = tid & 31;
    const int wm = wid & 3, wn = wid >> 2;
    const int rowB = blockIdx.y * 128, colB = blockIdx.x * 128;
    const __nv_bfloat16* Ag = A + (size_t)rowB * lda;
    const __nv_bfloat16* Bg = B + (size_t)colB * ldb;

    float acc[2][8][4];
#pragma unroll
    for (int i = 0; i < 2; i++)
#pragma unroll
        for (int j = 0; j < 8; j++)
#pragma unroll
            for (int k = 0; k < 4; k++) acc[i][j][k] = 0.f;

    const int NCH = K >> 6;
    cp_chunk64(as0, Ag, lda, tid); cp_chunk64(bs0, Bg, ldb, tid); CP_COMMIT;
    cp_chunk64(as0 + STG_B, Ag + 64, lda, tid); cp_chunk64(bs0 + STG_B, Bg + 64, ldb, tid); CP_COMMIT;

    for (int kc = 0; kc < NCH; kc++) {
        if (kc == NCH - 1) { CP_WAIT0; } else { CP_WAIT1; }
        __syncthreads();
        if (kc + 2 < NCH) {
            int st = (kc + 2) % 3;
            cp_chunk64(as0 + st * STG_B, Ag + (kc + 2) * 64, lda, tid);
            cp_chunk64(bs0 + st * STG_B, Bg + (kc + 2) * 64, ldb, tid);
            CP_COMMIT;
        }
        const int st = kc % 3;
        const uint32_t abase = as0 + st * STG_B, bbase = bs0 + st * STG_B;
#pragma unroll
        for (int ks = 0; ks < 64; ks += 16) {
            uint32_t a[2][4];
#pragma unroll
            for (int mt = 0; mt < 2; mt++) {
                int row = wm * 32 + mt * 16 + (lane & 7) + ((lane >> 3) & 1) * 8;
                int col = ks + ((lane >> 4) & 1) * 8;
                ldmx4(a[mt], abase + (uint32_t)(row * KPG + col) * 2);
            }
            uint32_t bf[8][2];
#pragma unroll
            for (int nb = 0; nb < 4; nb++) {
                int row = wn * 64 + nb * 16 + (lane & 7) + ((lane >> 4) & 1) * 8;
                int col = ks + ((lane >> 3) & 1) * 8;
                uint32_t r[4];
                ldmx4(r, bbase + (uint32_t)(row * KPG + col) * 2);
                bf[2 * nb][0] = r[0]; bf[2 * nb][1] = r[1];
                bf[2 * nb + 1][0] = r[2]; bf[2 * nb + 1][1] = r[3];
            }
#pragma unroll
            for (int mt = 0; mt < 2; mt++)
#pragma unroll
                for (int nt = 0; nt < 8; nt++)
                    mma16816(acc[mt][nt], a[mt], bf[nt]);
        }
    }

#pragma unroll
    for (int mt = 0; mt < 2; mt++) {
#pragma unroll
        for (int nt = 0; nt < 8; nt++) {
            const float* ac = acc[mt][nt];
            const int r0 = rowB + wm * 32 + mt * 16 + (lane >> 2);
            const int c = colB + wn * 64 + nt * 8 + (lane & 3) * 2;
            const float b0 = bias[c], b1 = bias[c + 1];
            if (EPI == 2) {
                float* C = (float*)Cout;
                float2 ra = *(const float2*)(res + (size_t)r0 * ldc + c);
                float2 rb = *(const float2*)(res + (size_t)(r0 + 8) * ldc + c);
                float2 o0 = { ac[0] + b0 + ra.x, ac[1] + b1 + ra.y };
                float2 o1 = { ac[2] + b0 + rb.x, ac[3] + b1 + rb.y };
                *(float2*)(C + (size_t)r0 * ldc + c) = o0;
                *(float2*)(C + (size_t)(r0 + 8) * ldc + c) = o1;
            } else {
                __nv_bfloat16* C = (__nv_bfloat16*)Cout;
                float v0 = ac[0] + b0, v1 = ac[1] + b1;
                float v2 = ac[2] + b0, v3 = ac[3] + b1;
                if (EPI == 1) { v0 = gelu_f(v0); v1 = gelu_f(v1); v2 = gelu_f(v2); v3 = gelu_f(v3); }
                *(uint32_t*)(C + (size_t)r0 * ldc + c) = pack_bf2(v0, v1);
                *(uint32_t*)(C + (size_t)(r0 + 8) * ldc + c) = pack_bf2(v2, v3);
            }
        }
    }
}

// ---------------- launch ----------------
extern "C" void kernel_launch(void* const* d_in, const int* in_sizes, int n_in,
                              void* d_out, int out_size)
{
    (void)in_sizes; (void)n_in; (void)out_size;
    const float* hidden  = (const float*)d_in[0];
    const float* alibi   = (const float*)d_in[1];
    const float* qkv_w   = (const float*)d_in[2];
    const float* qkv_b   = (const float*)d_in[3];
    const float* dense_w = (const float*)d_in[4];
    const float* dense_b = (const float*)d_in[5];
    const float* w1      = (const float*)d_in[6];
    const float* b1      = (const float*)d_in[7];
    const float* w2      = (const float*)d_in[8];
    const float* b2      = (const float*)d_in[9];
    const float* ln1w    = (const float*)d_in[10];
    const float* ln1b    = (const float*)d_in[11];
    const float* ln2w    = (const float*)d_in[12];
    const float* ln2b    = (const float*)d_in[13];
    float* x = (float*)d_out;

    __nv_bfloat16 *ph, *pqkv, *pvt, *pctx, *pff, *pwq, *pwd, *pw1, *pw2;
    cudaGetSymbolAddress((void**)&ph,   g_h);
    cudaGetSymbolAddress((void**)&pqkv, g_qkv);
    cudaGetSymbolAddress((void**)&pvt,  g_vt);
    cudaGetSymbolAddress((void**)&pctx, g_ctx);
    cudaGetSymbolAddress((void**)&pff,  g_ff);
    cudaGetSymbolAddress((void**)&pwq,  g_wq);
    cudaGetSymbolAddress((void**)&pwd,  g_wd);
    cudaGetSymbolAddress((void**)&pw1,  g_w1);
    cudaGetSymbolAddress((void**)&pw2,  g_w2);

    const int GEMM_SMEM  = 6 * STG_B;                                  // 110592
    const int FLASH_SMEM = (3 * 128 * KPQ + 2 * 64 * KPV) * 2;         // 90112
    cudaFuncSetAttribute(mm_gemm<0>, cudaFuncAttributeMaxDynamicSharedMemorySize, GEMM_SMEM);
    cudaFuncSetAttribute(mm_gemm<1>, cudaFuncAttributeMaxDynamicSharedMemorySize, GEMM_SMEM);
    cudaFuncSetAttribute(mm_gemm<2>, cudaFuncAttributeMaxDynamicSharedMemorySize, GEMM_SMEM);
    cudaFuncSetAttribute(flash_kernel, cudaFuncAttributeMaxDynamicSharedMemorySize, FLASH_SMEM);

    cudaMemcpyAsync(x, hidden, sizeof(float) * (size_t)NTOK * HID, cudaMemcpyDeviceToDevice);

    // weights -> bf16 (all 4 arrays in one launch)
    const int nq = NLAYER * QKVDIM * HID / 4, nd = NLAYER * HID * HID / 4;
    const int n1 = NLAYER * FFDIM * HID / 4, n2 = NLAYER * HID * FFDIM / 4;
    int nmax = n1 > nq ? n1 : nq;
    cvt4_kernel<<<dim3((nmax + 255) / 256, 4), 256>>>(
        qkv_w, pwq, nq, dense_w, pwd, nd, w1, pw1, n1, w2, pw2, n2);

    for (int l = 0; l < NLAYER; l++) {
        // --- attention ---
        ln_kernel<<<NTOK, 256>>>(x, ln1w + l * HID, ln1b + l * HID, ph);
        mm_gemm<0><<<dim3(QKVDIM / 128, NTOK / 128), 256, GEMM_SMEM>>>(
            ph, HID, pwq + (size_t)l * QKVDIM * HID, HID,
            qkv_b + (size_t)l * QKVDIM, nullptr, pqkv, QKVDIM, HID);
        vtrans_kernel<<<dim3(SEQ / 64, 1, BATCH * NHEAD), 256>>>(pqkv, pvt);
        flash_kernel<<<dim3(SEQ / 128, BATCH * NHEAD), 256, FLASH_SMEM>>>(pqkv, pvt, alibi, pctx);
        mm_gemm<2><<<dim3(HID / 128, NTOK / 128), 256, GEMM_SMEM>>>(
            pctx, HID, pwd + (size_t)l * HID * HID, HID,
            dense_b + (size_t)l * HID, x, x, HID, HID);
        // --- MLP ---
        ln_kernel<<<NTOK, 256>>>(x, ln2w + l * HID, ln2b + l * HID, ph);
        mm_gemm<1><<<dim3(FFDIM / 128, NTOK / 128), 256, GEMM_SMEM>>>(
            ph, HID, pw1 + (size_t)l * FFDIM * HID, HID,
            b1 + (size_t)l * FFDIM, nullptr, pff, FFDIM, HID);
        mm_gemm<2><<<dim3(HID / 128, NTOK / 128), 256, GEMM_SMEM>>>(
            pff, FFDIM, pw2 + (size_t)l * HID * FFDIM, FFDIM,
            b2 + (size_t)l * HID, x, x, HID, FFDIM);
    }
}

// round 10
// speedup vs baseline: 1.2683x; 1.1650x over previous
#include <cuda_runtime.h>
#include <cuda_bf16.h>
#include <math.h>
#include <stdint.h>

#define NLAYER 2
#define BATCH  2
#define SEQ    2048
#define HID    1024
#define NHEAD  16
#define DHEAD  64
#define FFDIM  4096
#define NTOK   (BATCH*SEQ)      // 4096
#define QKVDIM (3*HID)          // 3072
#define KPAD   40               // GEMM: 32-elem K chunk padded to 40
#define KPQ    72               // flash: 64-elem rows padded to 72
#define KPV    136              // flash: 128-elem rows padded to 136

// ---------------- scratch (device globals) ----------------
__device__ __nv_bfloat16 g_h[NTOK*HID];
__device__ __nv_bfloat16 g_qkv[(size_t)NTOK*QKVDIM];
__device__ __nv_bfloat16 g_vt[(size_t)BATCH*NHEAD*DHEAD*SEQ];
__device__ __nv_bfloat16 g_ctx[NTOK*HID];
__device__ __nv_bfloat16 g_ff[(size_t)NTOK*FFDIM];
__device__ __nv_bfloat16 g_wq[(size_t)NLAYER*QKVDIM*HID];
__device__ __nv_bfloat16 g_wd[(size_t)NLAYER*HID*HID];
__device__ __nv_bfloat16 g_w1[(size_t)NLAYER*FFDIM*HID];
__device__ __nv_bfloat16 g_w2[(size_t)NLAYER*HID*FFDIM];

// ---------------- helpers ----------------
__device__ __forceinline__ uint32_t smem_u32(const void* p) {
    uint32_t a;
    asm("{ .reg .u64 t; cvta.to.shared.u64 t, %1; cvt.u32.u64 %0, t; }" : "=r"(a) : "l"(p));
    return a;
}
__device__ __forceinline__ void cp16(uint32_t s, const void* g) {
    asm volatile("cp.async.cg.shared.global [%0], [%1], 16;" :: "r"(s), "l"(g));
}
#define CP_COMMIT asm volatile("cp.async.commit_group;")
#define CP_WAIT2  asm volatile("cp.async.wait_group 2;")
#define CP_WAIT1  asm volatile("cp.async.wait_group 1;")
#define CP_WAIT0  asm volatile("cp.async.wait_group 0;")

__device__ __forceinline__ void ldmx4(uint32_t* r, uint32_t addr) {
    asm volatile("ldmatrix.sync.aligned.m8n8.x4.shared.b16 {%0,%1,%2,%3}, [%4];"
                 : "=r"(r[0]), "=r"(r[1]), "=r"(r[2]), "=r"(r[3]) : "r"(addr));
}
__device__ __forceinline__ void mma16816(float* c, const uint32_t* a, const uint32_t* b) {
    asm volatile("mma.sync.aligned.m16n8k16.row.col.f32.bf16.bf16.f32 "
                 "{%0,%1,%2,%3}, {%4,%5,%6,%7}, {%8,%9}, {%0,%1,%2,%3};"
                 : "+f"(c[0]), "+f"(c[1]), "+f"(c[2]), "+f"(c[3])
                 : "r"(a[0]), "r"(a[1]), "r"(a[2]), "r"(a[3]), "r"(b[0]), "r"(b[1]));
}
__device__ __forceinline__ uint32_t pack_bf2(float a, float b) {
    __nv_bfloat162 h = __floats2bfloat162_rn(a, b);
    return *(uint32_t*)&h;
}
__device__ __forceinline__ float gelu_f(float v) {
    return 0.5f * v * (1.0f + erff(v * 0.70710678118654752440f));
}
__device__ __forceinline__ float warpSum(float v) {
#pragma unroll
    for (int o = 16; o > 0; o >>= 1) v += __shfl_xor_sync(0xffffffffu, v, o);
    return v;
}

// load 128 x 32 bf16 chunk from g (row stride ld elems) into smem (KPAD-elem rows)
__device__ __forceinline__ void cp_chunk(uint32_t sbase, const __nv_bfloat16* g, int ld, int tid) {
#pragma unroll
    for (int it = 0; it < 2; it++) {
        int idx = tid + it * 256;
        int row = idx >> 2, q = idx & 3;
        cp16(sbase + (uint32_t)(row * KPAD + q * 8) * 2, g + (size_t)row * ld + q * 8);
    }
}

// ---------------- LayerNorm (fp32 in, bf16 out) ----------------
__global__ __launch_bounds__(256)
void ln_kernel(const float* __restrict__ x, const float* __restrict__ w,
               const float* __restrict__ b, __nv_bfloat16* __restrict__ out)
{
    __shared__ float sh[8];
    __shared__ float stat;
    const int t = blockIdx.x;
    const float* xr = x + (size_t)t * HID;
    const int lane = threadIdx.x & 31, wp = threadIdx.x >> 5;

    float v[4];
    float s = 0.f;
#pragma unroll
    for (int i = 0; i < 4; i++) { v[i] = xr[threadIdx.x + i * 256]; s += v[i]; }
    s = warpSum(s);
    if (lane == 0) sh[wp] = s;
    __syncthreads();
    if (threadIdx.x == 0) {
        float r = 0.f;
#pragma unroll
        for (int i = 0; i < 8; i++) r += sh[i];
        stat = r * (1.0f / HID);
    }
    __syncthreads();
    const float mu = stat;

    float s2 = 0.f;
#pragma unroll
    for (int i = 0; i < 4; i++) { float d = v[i] - mu; s2 += d * d; }
    s2 = warpSum(s2);
    __syncthreads();
    if (lane == 0) sh[wp] = s2;
    __syncthreads();
    if (threadIdx.x == 0) {
        float r = 0.f;
#pragma unroll
        for (int i = 0; i < 8; i++) r += sh[i];
        stat = rsqrtf(r * (1.0f / HID) + 1e-5f);
    }
    __syncthreads();
    const float rs = stat;

    __nv_bfloat16* orow = out + (size_t)t * HID;
#pragma unroll
    for (int i = 0; i < 4; i++) {
        int c = threadIdx.x + i * 256;
        orow[c] = __float2bfloat16((v[i] - mu) * rs * w[c] + b[c]);
    }
}

// ---------------- merged weight convert fp32 -> bf16 (4 arrays via grid.y) ----------
__global__ __launch_bounds__(256)
void cvt4_kernel(const float* __restrict__ s0, __nv_bfloat16* __restrict__ d0, int n0,
                 const float* __restrict__ s1, __nv_bfloat16* __restrict__ d1, int n1,
                 const float* __restrict__ s2, __nv_bfloat16* __restrict__ d2, int n2,
                 const float* __restrict__ s3, __nv_bfloat16* __restrict__ d3, int n3)
{
    const float* src; __nv_bfloat16* dst; int n;
    switch (blockIdx.y) {
        case 0: src = s0; dst = d0; n = n0; break;
        case 1: src = s1; dst = d1; n = n1; break;
        case 2: src = s2; dst = d2; n = n2; break;
        default: src = s3; dst = d3; n = n3; break;
    }
    int i = blockIdx.x * 256 + threadIdx.x;
    if (i < n) {
        float4 v = ((const float4*)src)[i];
        uint2 o;
        o.x = pack_bf2(v.x, v.y);
        o.y = pack_bf2(v.z, v.w);
        ((uint2*)dst)[i] = o;
    }
}

// ---------------- V transpose: 64x64 tiles, vectorized ----------------
// grid (SEQ/64, 1, B*NH), 256 threads
__global__ __launch_bounds__(256)
void vtrans_kernel(const __nv_bfloat16* __restrict__ qkv, __nv_bfloat16* __restrict__ vt)
{
    __shared__ __nv_bfloat16 t[64 * KPQ];
    const int z = blockIdx.z, b = z >> 4, h = z & 15;
    const int s0 = blockIdx.x * 64;
    const int tid = threadIdx.x;
#pragma unroll
    for (int it = 0; it < 2; it++) {
        int idx = tid + it * 256;
        int srow = idx >> 3, d8 = (idx & 7) * 8;
        const __nv_bfloat16* src = qkv + (size_t)(b * SEQ + s0 + srow) * QKVDIM + 2 * HID + h * DHEAD + d8;
        *(uint4*)&t[srow * KPQ + d8] = *(const uint4*)src;
    }
    __syncthreads();
#pragma unroll
    for (int half = 0; half < 2; half++) {
        int drow = (tid >> 3) + half * 32, s8 = (tid & 7) * 8;
        __nv_bfloat16 vbuf[8];
#pragma unroll
        for (int i = 0; i < 8; i++) vbuf[i] = t[(s8 + i) * KPQ + drow];
        *(uint4*)(vt + (size_t)z * DHEAD * SEQ + (size_t)drow * SEQ + s0 + s8) = *(uint4*)vbuf;
    }
}

// ---------------- flash attention: ctx = softmax(QK^T/8 + alibi, causal) V ----------
// grid (16 qtiles [reversed], B*NH). 8 warps, each owns 16 q-rows x full 128 k-tile.
__global__ __launch_bounds__(256)
void flash_kernel(const __nv_bfloat16* __restrict__ qkv,
                  const __nv_bfloat16* __restrict__ vt,
                  const float* __restrict__ alibi,
                  __nv_bfloat16* __restrict__ ctx)
{
    extern __shared__ __nv_bfloat16 sm[];
    const int tid = threadIdx.x, wid = tid >> 5, lane = tid & 31;
    const int qt = (int)gridDim.x - 1 - (int)blockIdx.x;   // big tiles first
    const int z = blockIdx.y, b = z >> 4, h = z & 15;

    const uint32_t qsa = smem_u32(sm);                              // Q: 128 x KPQ
    const uint32_t ksa[2] = { qsa + 128 * KPQ * 2, qsa + 2 * 128 * KPQ * 2 };
    const uint32_t vsa[2] = { qsa + 3 * 128 * KPQ * 2, qsa + 3 * 128 * KPQ * 2 + 64 * KPV * 2 };

    const __nv_bfloat16* Qg = qkv + ((size_t)(b * SEQ) + qt * 128) * QKVDIM + h * DHEAD;
    const __nv_bfloat16* Kg = qkv + (size_t)(b * SEQ) * QKVDIM + HID + h * DHEAD;
    const __nv_bfloat16* Vg = vt + (size_t)z * DHEAD * SEQ;
    const float slope = alibi[(size_t)z * SEQ + 1];   // alibi[...,c] == slope*c exactly

    {
#pragma unroll
        for (int it = 0; it < 4; it++) {
            int idx = tid + it * 256, row = idx >> 3, u = idx & 7;
            cp16(qsa + (uint32_t)(row * KPQ + u * 8) * 2, Qg + (size_t)row * QKVDIM + u * 8);
        }
#pragma unroll
        for (int it = 0; it < 4; it++) {
            int idx = tid + it * 256, row = idx >> 3, u = idx & 7;
            cp16(ksa[0] + (uint32_t)(row * KPQ + u * 8) * 2, Kg + (size_t)row * QKVDIM + u * 8);
        }
#pragma unroll
        for (int it = 0; it < 4; it++) {
            int idx = tid + it * 256, row = idx >> 4, u = idx & 15;
            cp16(vsa[0] + (uint32_t)(row * KPV + u * 8) * 2, Vg + (size_t)row * SEQ + u * 8);
        }
        CP_COMMIT;
    }
    CP_WAIT0;
    __syncthreads();

    uint32_t aQ[4][4];
#pragma unroll
    for (int kc = 0; kc < 4; kc++) {
        int row = wid * 16 + (lane & 7) + ((lane >> 3) & 1) * 8;
        int col = kc * 16 + ((lane >> 4) & 1) * 8;
        ldmx4(aQ[kc], qsa + (uint32_t)(row * KPQ + col) * 2);
    }

    float m0 = -1e30f, m1 = -1e30f, l0 = 0.f, l1 = 0.f;
    float oacc[8][4];
#pragma unroll
    for (int i = 0; i < 8; i++)
#pragma unroll
        for (int j = 0; j < 4; j++) oacc[i][j] = 0.f;

    const int rg0 = qt * 128 + wid * 16 + (lane >> 2);
    const int rg1 = rg0 + 8;

    for (int kt = 0; kt <= qt; kt++) {
        const int cur = kt & 1;
        if (kt < qt) {
            const __nv_bfloat16* Kn = Kg + (size_t)(kt + 1) * 128 * QKVDIM;
            const __nv_bfloat16* Vn = Vg + (kt + 1) * 128;
#pragma unroll
            for (int it = 0; it < 4; it++) {
                int idx = tid + it * 256, row = idx >> 3, u = idx & 7;
                cp16(ksa[cur ^ 1] + (uint32_t)(row * KPQ + u * 8) * 2, Kn + (size_t)row * QKVDIM + u * 8);
            }
#pragma unroll
            for (int it = 0; it < 4; it++) {
                int idx = tid + it * 256, row = idx >> 4, u = idx & 15;
                cp16(vsa[cur ^ 1] + (uint32_t)(row * KPV + u * 8) * 2, Vn + (size_t)row * SEQ + u * 8);
            }
            CP_COMMIT;
        }

        float sacc[16][4];
#pragma unroll
        for (int i = 0; i < 16; i++)
#pragma unroll
            for (int j = 0; j < 4; j++) sacc[i][j] = 0.f;
#pragma unroll
        for (int kc = 0; kc < 4; kc++) {
#pragma unroll
            for (int nb = 0; nb < 8; nb++) {
                uint32_t r[4];
                int row = nb * 16 + (lane & 7) + ((lane >> 4) & 1) * 8;
                int col = kc * 16 + ((lane >> 3) & 1) * 8;
                ldmx4(r, ksa[cur] + (uint32_t)(row * KPQ + col) * 2);
                mma16816(sacc[2 * nb], aQ[kc], r);
                mma16816(sacc[2 * nb + 1], aQ[kc], r + 2);
            }
        }

        float mx0 = -1e30f, mx1 = -1e30f;
        const int cb = kt * 128 + (lane & 3) * 2;
#pragma unroll
        for (int nt = 0; nt < 16; nt++) {
            int c0 = cb + nt * 8, c1 = c0 + 1;
            float a0 = slope * (float)c0, a1 = slope * (float)c1;
            float s0 = (c0 <= rg0) ? fmaf(sacc[nt][0], 0.125f, a0) : -1e30f;
            float s1 = (c1 <= rg0) ? fmaf(sacc[nt][1], 0.125f, a1) : -1e30f;
            float s2 = (c0 <= rg1) ? fmaf(sacc[nt][2], 0.125f, a0) : -1e30f;
            float s3 = (c1 <= rg1) ? fmaf(sacc[nt][3], 0.125f, a1) : -1e30f;
            sacc[nt][0] = s0; sacc[nt][1] = s1; sacc[nt][2] = s2; sacc[nt][3] = s3;
            mx0 = fmaxf(mx0, fmaxf(s0, s1)); mx1 = fmaxf(mx1, fmaxf(s2, s3));
        }
        mx0 = fmaxf(mx0, __shfl_xor_sync(0xffffffffu, mx0, 1));
        mx0 = fmaxf(mx0, __shfl_xor_sync(0xffffffffu, mx0, 2));
        mx1 = fmaxf(mx1, __shfl_xor_sync(0xffffffffu, mx1, 1));
        mx1 = fmaxf(mx1, __shfl_xor_sync(0xffffffffu, mx1, 2));

        const float mn0 = fmaxf(m0, mx0), mn1 = fmaxf(m1, mx1);
        const float sc0 = __expf(m0 - mn0), sc1 = __expf(m1 - mn1);
        float rs0 = 0.f, rs1 = 0.f;
#pragma unroll
        for (int nt = 0; nt < 16; nt++) {
            float p0 = __expf(sacc[nt][0] - mn0), p1 = __expf(sacc[nt][1] - mn0);
            float p2 = __expf(sacc[nt][2] - mn1), p3 = __expf(sacc[nt][3] - mn1);
            sacc[nt][0] = p0; sacc[nt][1] = p1; sacc[nt][2] = p2; sacc[nt][3] = p3;
            rs0 += p0 + p1; rs1 += p2 + p3;
        }
        rs0 += __shfl_xor_sync(0xffffffffu, rs0, 1);
        rs0 += __shfl_xor_sync(0xffffffffu, rs0, 2);
        rs1 += __shfl_xor_sync(0xffffffffu, rs1, 1);
        rs1 += __shfl_xor_sync(0xffffffffu, rs1, 2);
        l0 = l0 * sc0 + rs0; l1 = l1 * sc1 + rs1;
        m0 = mn0; m1 = mn1;
#pragma unroll
        for (int nt = 0; nt < 8; nt++) {
            oacc[nt][0] *= sc0; oacc[nt][1] *= sc0;
            oacc[nt][2] *= sc1; oacc[nt][3] *= sc1;
        }

#pragma unroll
        for (int kc2 = 0; kc2 < 8; kc2++) {
            uint32_t pa[4] = {
                pack_bf2(sacc[2 * kc2][0],     sacc[2 * kc2][1]),
                pack_bf2(sacc[2 * kc2][2],     sacc[2 * kc2][3]),
                pack_bf2(sacc[2 * kc2 + 1][0], sacc[2 * kc2 + 1][1]),
                pack_bf2(sacc[2 * kc2 + 1][2], sacc[2 * kc2 + 1][3]) };
#pragma unroll
            for (int nb = 0; nb < 4; nb++) {
                uint32_t r[4];
                int row = nb * 16 + (lane & 7) + ((lane >> 4) & 1) * 8;
                int col = kc2 * 16 + ((lane >> 3) & 1) * 8;
                ldmx4(r, vsa[cur] + (uint32_t)(row * KPV + col) * 2);
                mma16816(oacc[2 * nb], pa, r);
                mma16816(oacc[2 * nb + 1], pa, r + 2);
            }
        }

        if (kt < qt) CP_WAIT0;
        __syncthreads();
    }

    const float inv0 = 1.0f / l0, inv1 = 1.0f / l1;
    const int tok0 = b * SEQ + qt * 128 + wid * 16 + (lane >> 2);
#pragma unroll
    for (int nt = 0; nt < 8; nt++) {
        int c = h * DHEAD + nt * 8 + (lane & 3) * 2;
        *(uint32_t*)(ctx + (size_t)tok0 * HID + c) = pack_bf2(oacc[nt][0] * inv0, oacc[nt][1] * inv0);
        *(uint32_t*)(ctx + (size_t)(tok0 + 8) * HID + c) = pack_bf2(oacc[nt][2] * inv1, oacc[nt][3] * inv1);
    }
}

// ---------------- bf16 NT GEMM: 256 threads, warp tile 32x64, K-chunk 32, 4-stage ----
// EPI: 0 = bias -> bf16, 1 = bias+gelu -> bf16, 2 = bias+residual -> fp32
#define STG_B (128 * KPAD * 2)   // bytes per stage per operand (10240)
#define NSTG  4

template<int EPI>
__global__ __launch_bounds__(256, 2)
void mm_gemm(const __nv_bfloat16* __restrict__ A, int lda,
             const __nv_bfloat16* __restrict__ B, int ldb,
             const float* __restrict__ bias, const float* __restrict__ res,
             void* __restrict__ Cout, int ldc, int K)
{
    extern __shared__ __nv_bfloat16 smbuf[];
    const uint32_t as0 = smem_u32(smbuf);
    const uint32_t bs0 = as0 + NSTG * STG_B;
    const int tid = threadIdx.x, wid = tid >> 5, lane = tid & 31;
    const int wm = wid & 3, wn = wid >> 2;
    const int rowB = blockIdx.y * 128, colB = blockIdx.x * 128;
    const __nv_bfloat16* Ag = A + (size_t)rowB * lda;
    const __nv_bfloat16* Bg = B + (size_t)colB * ldb;

    float acc[2][8][4];
#pragma unroll
    for (int i = 0; i < 2; i++)
#pragma unroll
        for (int j = 0; j < 8; j++)
#pragma unroll
            for (int k = 0; k < 4; k++) acc[i][j][k] = 0.f;

    const int NCH = K >> 5;
    int committed = 0;
#pragma unroll
    for (int p = 0; p < 3; p++) {
        if (p < NCH) {
            cp_chunk(as0 + p * STG_B, Ag + p * 32, lda, tid);
            cp_chunk(bs0 + p * STG_B, Bg + p * 32, ldb, tid);
            CP_COMMIT;
            committed++;
        }
    }

    for (int kc = 0; kc < NCH; kc++) {
        const int pend = committed - kc - 1;
        if (pend >= 2) { CP_WAIT2; } else if (pend == 1) { CP_WAIT1; } else { CP_WAIT0; }
        __syncthreads();
        if (committed < NCH) {
            int st = committed & (NSTG - 1);
            cp_chunk(as0 + st * STG_B, Ag + committed * 32, lda, tid);
            cp_chunk(bs0 + st * STG_B, Bg + committed * 32, ldb, tid);
            CP_COMMIT;
            committed++;
        }
        const int st = kc & (NSTG - 1);
        const uint32_t abase = as0 + st * STG_B, bbase = bs0 + st * STG_B;
#pragma unroll
        for (int ks = 0; ks < 32; ks += 16) {
            uint32_t a[2][4];
#pragma unroll
            for (int mt = 0; mt < 2; mt++) {
                int row = wm * 32 + mt * 16 + (lane & 7) + ((lane >> 3) & 1) * 8;
                int col = ks + ((lane >> 4) & 1) * 8;
                ldmx4(a[mt], abase + (uint32_t)(row * KPAD + col) * 2);
            }
            uint32_t bf[8][2];
#pragma unroll
            for (int nb = 0; nb < 4; nb++) {
                int row = wn * 64 + nb * 16 + (lane & 7) + ((lane >> 4) & 1) * 8;
                int col = ks + ((lane >> 3) & 1) * 8;
                uint32_t r[4];
                ldmx4(r, bbase + (uint32_t)(row * KPAD + col) * 2);
                bf[2 * nb][0] = r[0]; bf[2 * nb][1] = r[1];
                bf[2 * nb + 1][0] = r[2]; bf[2 * nb + 1][1] = r[3];
            }
#pragma unroll
            for (int mt = 0; mt < 2; mt++)
#pragma unroll
                for (int nt = 0; nt < 8; nt++)
                    mma16816(acc[mt][nt], a[mt], bf[nt]);
        }
    }

#pragma unroll
    for (int mt = 0; mt < 2; mt++) {
#pragma unroll
        for (int nt = 0; nt < 8; nt++) {
            const float* ac = acc[mt][nt];
            const int r0 = rowB + wm * 32 + mt * 16 + (lane >> 2);
            const int c = colB + wn * 64 + nt * 8 + (lane & 3) * 2;
            const float b0 = bias[c], b1 = bias[c + 1];
            if (EPI == 2) {
                float* C = (float*)Cout;
                float2 ra = *(const float2*)(res + (size_t)r0 * ldc + c);
                float2 rb = *(const float2*)(res + (size_t)(r0 + 8) * ldc + c);
                float2 o0 = { ac[0] + b0 + ra.x, ac[1] + b1 + ra.y };
                float2 o1 = { ac[2] + b0 + rb.x, ac[3] + b1 + rb.y };
                *(float2*)(C + (size_t)r0 * ldc + c) = o0;
                *(float2*)(C + (size_t)(r0 + 8) * ldc + c) = o1;
            } else {
                __nv_bfloat16* C = (__nv_bfloat16*)Cout;
                float v0 = ac[0] + b0, v1 = ac[1] + b1;
                float v2 = ac[2] + b0, v3 = ac[3] + b1;
                if (EPI == 1) { v0 = gelu_f(v0); v1 = gelu_f(v1); v2 = gelu_f(v2); v3 = gelu_f(v3); }
                *(uint32_t*)(C + (size_t)r0 * ldc + c) = pack_bf2(v0, v1);
                *(uint32_t*)(C + (size_t)(r0 + 8) * ldc + c) = pack_bf2(v2, v3);
            }
        }
    }
}

// ---------------- launch ----------------
extern "C" void kernel_launch(void* const* d_in, const int* in_sizes, int n_in,
                              void* d_out, int out_size)
{
    (void)in_sizes; (void)n_in; (void)out_size;
    const float* hidden  = (const float*)d_in[0];
    const float* alibi   = (const float*)d_in[1];
    const float* qkv_w   = (const float*)d_in[2];
    const float* qkv_b   = (const float*)d_in[3];
    const float* dense_w = (const float*)d_in[4];
    const float* dense_b = (const float*)d_in[5];
    const float* w1      = (const float*)d_in[6];
    const float* b1      = (const float*)d_in[7];
    const float* w2      = (const float*)d_in[8];
    const float* b2      = (const float*)d_in[9];
    const float* ln1w    = (const float*)d_in[10];
    const float* ln1b    = (const float*)d_in[11];
    const float* ln2w    = (const float*)d_in[12];
    const float* ln2b    = (const float*)d_in[13];
    float* x = (float*)d_out;

    __nv_bfloat16 *ph, *pqkv, *pvt, *pctx, *pff, *pwq, *pwd, *pw1, *pw2;
    cudaGetSymbolAddress((void**)&ph,   g_h);
    cudaGetSymbolAddress((void**)&pqkv, g_qkv);
    cudaGetSymbolAddress((void**)&pvt,  g_vt);
    cudaGetSymbolAddress((void**)&pctx, g_ctx);
    cudaGetSymbolAddress((void**)&pff,  g_ff);
    cudaGetSymbolAddress((void**)&pwq,  g_wq);
    cudaGetSymbolAddress((void**)&pwd,  g_wd);
    cudaGetSymbolAddress((void**)&pw1,  g_w1);
    cudaGetSymbolAddress((void**)&pw2,  g_w2);

    const int GEMM_SMEM  = 2 * NSTG * STG_B;                           // 81920
    const int FLASH_SMEM = (3 * 128 * KPQ + 2 * 64 * KPV) * 2;         // 90112
    cudaFuncSetAttribute(mm_gemm<0>, cudaFuncAttributeMaxDynamicSharedMemorySize, GEMM_SMEM);
    cudaFuncSetAttribute(mm_gemm<1>, cudaFuncAttributeMaxDynamicSharedMemorySize, GEMM_SMEM);
    cudaFuncSetAttribute(mm_gemm<2>, cudaFuncAttributeMaxDynamicSharedMemorySize, GEMM_SMEM);
    cudaFuncSetAttribute(flash_kernel, cudaFuncAttributeMaxDynamicSharedMemorySize, FLASH_SMEM);

    cudaMemcpyAsync(x, hidden, sizeof(float) * (size_t)NTOK * HID, cudaMemcpyDeviceToDevice);

    // weights -> bf16 (all 4 arrays in one launch)
    const int nq = NLAYER * QKVDIM * HID / 4, nd = NLAYER * HID * HID / 4;
    const int n1 = NLAYER * FFDIM * HID / 4, n2 = NLAYER * HID * FFDIM / 4;
    int nmax = n1 > nq ? n1 : nq;
    cvt4_kernel<<<dim3((nmax + 255) / 256, 4), 256>>>(
        qkv_w, pwq, nq, dense_w, pwd, nd, w1, pw1, n1, w2, pw2, n2);

    for (int l = 0; l < NLAYER; l++) {
        // --- attention ---
        ln_kernel<<<NTOK, 256>>>(x, ln1w + l * HID, ln1b + l * HID, ph);
        mm_gemm<0><<<dim3(QKVDIM / 128, NTOK / 128), 256, GEMM_SMEM>>>(
            ph, HID, pwq + (size_t)l * QKVDIM * HID, HID,
            qkv_b + (size_t)l * QKVDIM, nullptr, pqkv, QKVDIM, HID);
        vtrans_kernel<<<dim3(SEQ / 64, 1, BATCH * NHEAD), 256>>>(pqkv, pvt);
        flash_kernel<<<dim3(SEQ / 128, BATCH * NHEAD), 256, FLASH_SMEM>>>(pqkv, pvt, alibi, pctx);
        mm_gemm<2><<<dim3(HID / 128, NTOK / 128), 256, GEMM_SMEM>>>(
            pctx, HID, pwd + (size_t)l * HID * HID, HID,
            dense_b + (size_t)l * HID, x, x, HID, HID);
        // --- MLP ---
        ln_kernel<<<NTOK, 256>>>(x, ln2w + l * HID, ln2b + l * HID, ph);
        mm_gemm<1><<<dim3(FFDIM / 128, NTOK / 128), 256, GEMM_SMEM>>>(
            ph, HID, pw1 + (size_t)l * FFDIM * HID, HID,
            b1 + (size_t)l * FFDIM, nullptr, pff, FFDIM, HID);
        mm_gemm<2><<<dim3(HID / 128, NTOK / 128), 256, GEMM_SMEM>>>(
            pff, FFDIM, pw2 + (size_t)l * HID * FFDIM, FFDIM,
            b2 + (size_t)l * HID, x, x, HID, FFDIM);
    }
}

// round 11
// speedup vs baseline: 1.3366x; 1.0538x over previous
#include <cuda_runtime.h>
#include <cuda_bf16.h>
#include <math.h>
#include <stdint.h>

#define NLAYER 2
#define BATCH  2
#define SEQ    2048
#define HID    1024
#define NHEAD  16
#define DHEAD  64
#define FFDIM  4096
#define NTOK   (BATCH*SEQ)      // 4096
#define QKVDIM (3*HID)          // 3072
#define KPAD   40               // GEMM: 32-elem K chunk padded to 40
#define KPQ    72               // flash: 64-elem rows padded to 72
#define KPV    136              // flash: 128-elem rows padded to 136

// ---------------- scratch (device globals) ----------------
__device__ __nv_bfloat16 g_h[NTOK*HID];
__device__ __nv_bfloat16 g_qkv[(size_t)NTOK*QKVDIM];
__device__ __nv_bfloat16 g_vt[(size_t)BATCH*NHEAD*DHEAD*SEQ];
__device__ __nv_bfloat16 g_ctx[NTOK*HID];
__device__ __nv_bfloat16 g_ff[(size_t)NTOK*FFDIM];
__device__ __nv_bfloat16 g_wq[(size_t)NLAYER*QKVDIM*HID];
__device__ __nv_bfloat16 g_wd[(size_t)NLAYER*HID*HID];
__device__ __nv_bfloat16 g_w1[(size_t)NLAYER*FFDIM*HID];
__device__ __nv_bfloat16 g_w2[(size_t)NLAYER*HID*FFDIM];

// ---------------- helpers ----------------
__device__ __forceinline__ uint32_t smem_u32(const void* p) {
    uint32_t a;
    asm("{ .reg .u64 t; cvta.to.shared.u64 t, %1; cvt.u32.u64 %0, t; }" : "=r"(a) : "l"(p));
    return a;
}
__device__ __forceinline__ void cp16(uint32_t s, const void* g) {
    asm volatile("cp.async.cg.shared.global [%0], [%1], 16;" :: "r"(s), "l"(g));
}
#define CP_COMMIT asm volatile("cp.async.commit_group;")
#define CP_WAIT1  asm volatile("cp.async.wait_group 1;")
#define CP_WAIT0  asm volatile("cp.async.wait_group 0;")

__device__ __forceinline__ void ldmx4(uint32_t* r, uint32_t addr) {
    asm volatile("ldmatrix.sync.aligned.m8n8.x4.shared.b16 {%0,%1,%2,%3}, [%4];"
                 : "=r"(r[0]), "=r"(r[1]), "=r"(r[2]), "=r"(r[3]) : "r"(addr));
}
__device__ __forceinline__ void mma16816(float* c, const uint32_t* a, const uint32_t* b) {
    asm volatile("mma.sync.aligned.m16n8k16.row.col.f32.bf16.bf16.f32 "
                 "{%0,%1,%2,%3}, {%4,%5,%6,%7}, {%8,%9}, {%0,%1,%2,%3};"
                 : "+f"(c[0]), "+f"(c[1]), "+f"(c[2]), "+f"(c[3])
                 : "r"(a[0]), "r"(a[1]), "r"(a[2]), "r"(a[3]), "r"(b[0]), "r"(b[1]));
}
__device__ __forceinline__ uint32_t pack_bf2(float a, float b) {
    __nv_bfloat162 h = __floats2bfloat162_rn(a, b);
    return *(uint32_t*)&h;
}
__device__ __forceinline__ float gelu_f(float v) {
    return 0.5f * v * (1.0f + erff(v * 0.70710678118654752440f));
}
__device__ __forceinline__ float warpSum(float v) {
#pragma unroll
    for (int o = 16; o > 0; o >>= 1) v += __shfl_xor_sync(0xffffffffu, v, o);
    return v;
}

// load 128 x 32 bf16 chunk from g (row stride ld elems) into smem (KPAD-elem rows)
__device__ __forceinline__ void cp_chunk(uint32_t sbase, const __nv_bfloat16* g, int ld, int tid) {
#pragma unroll
    for (int it = 0; it < 2; it++) {
        int idx = tid + it * 256;
        int row = idx >> 2, q = idx & 3;
        cp16(sbase + (uint32_t)(row * KPAD + q * 8) * 2, g + (size_t)row * ld + q * 8);
    }
}

// one 32-wide K-chunk of warp-level MMAs (128x128 CTA tile, 4x2 warps, 32x64 warp tile)
__device__ __forceinline__ void mma_chunk(float (&acc)[2][8][4], uint32_t abase, uint32_t bbase,
                                          int wm, int wn, int lane) {
#pragma unroll
    for (int ks = 0; ks < 32; ks += 16) {
        uint32_t a[2][4];
#pragma unroll
        for (int mt = 0; mt < 2; mt++) {
            int row = wm * 32 + mt * 16 + (lane & 7) + ((lane >> 3) & 1) * 8;
            int col = ks + ((lane >> 4) & 1) * 8;
            ldmx4(a[mt], abase + (uint32_t)(row * KPAD + col) * 2);
        }
        uint32_t bf[8][2];
#pragma unroll
        for (int nb = 0; nb < 4; nb++) {
            int row = wn * 64 + nb * 16 + (lane & 7) + ((lane >> 4) & 1) * 8;
            int col = ks + ((lane >> 3) & 1) * 8;
            uint32_t r[4];
            ldmx4(r, bbase + (uint32_t)(row * KPAD + col) * 2);
            bf[2 * nb][0] = r[0]; bf[2 * nb][1] = r[1];
            bf[2 * nb + 1][0] = r[2]; bf[2 * nb + 1][1] = r[3];
        }
#pragma unroll
        for (int mt = 0; mt < 2; mt++)
#pragma unroll
            for (int nt = 0; nt < 8; nt++)
                mma16816(acc[mt][nt], a[mt], bf[nt]);
    }
}

// ---------------- LayerNorm (fp32 in, bf16 out) ----------------
__global__ __launch_bounds__(256)
void ln_kernel(const float* __restrict__ x, const float* __restrict__ w,
               const float* __restrict__ b, __nv_bfloat16* __restrict__ out)
{
    __shared__ float sh[8];
    __shared__ float stat;
    const int t = blockIdx.x;
    const float* xr = x + (size_t)t * HID;
    const int lane = threadIdx.x & 31, wp = threadIdx.x >> 5;

    float v[4];
    float s = 0.f;
#pragma unroll
    for (int i = 0; i < 4; i++) { v[i] = xr[threadIdx.x + i * 256]; s += v[i]; }
    s = warpSum(s);
    if (lane == 0) sh[wp] = s;
    __syncthreads();
    if (threadIdx.x == 0) {
        float r = 0.f;
#pragma unroll
        for (int i = 0; i < 8; i++) r += sh[i];
        stat = r * (1.0f / HID);
    }
    __syncthreads();
    const float mu = stat;

    float s2 = 0.f;
#pragma unroll
    for (int i = 0; i < 4; i++) { float d = v[i] - mu; s2 += d * d; }
    s2 = warpSum(s2);
    __syncthreads();
    if (lane == 0) sh[wp] = s2;
    __syncthreads();
    if (threadIdx.x == 0) {
        float r = 0.f;
#pragma unroll
        for (int i = 0; i < 8; i++) r += sh[i];
        stat = rsqrtf(r * (1.0f / HID) + 1e-5f);
    }
    __syncthreads();
    const float rs = stat;

    __nv_bfloat16* orow = out + (size_t)t * HID;
#pragma unroll
    for (int i = 0; i < 4; i++) {
        int c = threadIdx.x + i * 256;
        orow[c] = __float2bfloat16((v[i] - mu) * rs * w[c] + b[c]);
    }
}

// ---------------- merged weight convert fp32 -> bf16 (4 arrays via grid.y) ----------
__global__ __launch_bounds__(256)
void cvt4_kernel(const float* __restrict__ s0, __nv_bfloat16* __restrict__ d0, int n0,
                 const float* __restrict__ s1, __nv_bfloat16* __restrict__ d1, int n1,
                 const float* __restrict__ s2, __nv_bfloat16* __restrict__ d2, int n2,
                 const float* __restrict__ s3, __nv_bfloat16* __restrict__ d3, int n3)
{
    const float* src; __nv_bfloat16* dst; int n;
    switch (blockIdx.y) {
        case 0: src = s0; dst = d0; n = n0; break;
        case 1: src = s1; dst = d1; n = n1; break;
        case 2: src = s2; dst = d2; n = n2; break;
        default: src = s3; dst = d3; n = n3; break;
    }
    int i = blockIdx.x * 256 + threadIdx.x;
    if (i < n) {
        float4 v = ((const float4*)src)[i];
        uint2 o;
        o.x = pack_bf2(v.x, v.y);
        o.y = pack_bf2(v.z, v.w);
        ((uint2*)dst)[i] = o;
    }
}

// ---------------- V transpose: 64x64 tiles, vectorized ----------------
// grid (SEQ/64, 1, B*NH), 256 threads
__global__ __launch_bounds__(256)
void vtrans_kernel(const __nv_bfloat16* __restrict__ qkv, __nv_bfloat16* __restrict__ vt)
{
    __shared__ __nv_bfloat16 t[64 * KPQ];
    const int z = blockIdx.z, b = z >> 4, h = z & 15;
    const int s0 = blockIdx.x * 64;
    const int tid = threadIdx.x;
#pragma unroll
    for (int it = 0; it < 2; it++) {
        int idx = tid + it * 256;
        int srow = idx >> 3, d8 = (idx & 7) * 8;
        const __nv_bfloat16* src = qkv + (size_t)(b * SEQ + s0 + srow) * QKVDIM + 2 * HID + h * DHEAD + d8;
        *(uint4*)&t[srow * KPQ + d8] = *(const uint4*)src;
    }
    __syncthreads();
#pragma unroll
    for (int half = 0; half < 2; half++) {
        int drow = (tid >> 3) + half * 32, s8 = (tid & 7) * 8;
        __nv_bfloat16 vbuf[8];
#pragma unroll
        for (int i = 0; i < 8; i++) vbuf[i] = t[(s8 + i) * KPQ + drow];
        *(uint4*)(vt + (size_t)z * DHEAD * SEQ + (size_t)drow * SEQ + s0 + s8) = *(uint4*)vbuf;
    }
}

// ---------------- flash attention: ctx = softmax(QK^T/8 + alibi, causal) V ----------
// grid (16 qtiles [reversed], B*NH). 8 warps, each owns 16 q-rows x full 128 k-tile.
__global__ __launch_bounds__(256)
void flash_kernel(const __nv_bfloat16* __restrict__ qkv,
                  const __nv_bfloat16* __restrict__ vt,
                  const float* __restrict__ alibi,
                  __nv_bfloat16* __restrict__ ctx)
{
    extern __shared__ __nv_bfloat16 sm[];
    const int tid = threadIdx.x, wid = tid >> 5, lane = tid & 31;
    const int qt = (int)gridDim.x - 1 - (int)blockIdx.x;   // big tiles first
    const int z = blockIdx.y, b = z >> 4, h = z & 15;

    const uint32_t qsa = smem_u32(sm);                              // Q: 128 x KPQ
    const uint32_t ksa[2] = { qsa + 128 * KPQ * 2, qsa + 2 * 128 * KPQ * 2 };
    const uint32_t vsa[2] = { qsa + 3 * 128 * KPQ * 2, qsa + 3 * 128 * KPQ * 2 + 64 * KPV * 2 };

    const __nv_bfloat16* Qg = qkv + ((size_t)(b * SEQ) + qt * 128) * QKVDIM + h * DHEAD;
    const __nv_bfloat16* Kg = qkv + (size_t)(b * SEQ) * QKVDIM + HID + h * DHEAD;
    const __nv_bfloat16* Vg = vt + (size_t)z * DHEAD * SEQ;
    const float slope = alibi[(size_t)z * SEQ + 1];   // alibi[...,c] == slope*c exactly

    {
#pragma unroll
        for (int it = 0; it < 4; it++) {
            int idx = tid + it * 256, row = idx >> 3, u = idx & 7;
            cp16(qsa + (uint32_t)(row * KPQ + u * 8) * 2, Qg + (size_t)row * QKVDIM + u * 8);
        }
#pragma unroll
        for (int it = 0; it < 4; it++) {
            int idx = tid + it * 256, row = idx >> 3, u = idx & 7;
            cp16(ksa[0] + (uint32_t)(row * KPQ + u * 8) * 2, Kg + (size_t)row * QKVDIM + u * 8);
        }
#pragma unroll
        for (int it = 0; it < 4; it++) {
            int idx = tid + it * 256, row = idx >> 4, u = idx & 15;
            cp16(vsa[0] + (uint32_t)(row * KPV + u * 8) * 2, Vg + (size_t)row * SEQ + u * 8);
        }
        CP_COMMIT;
    }
    CP_WAIT0;
    __syncthreads();

    uint32_t aQ[4][4];
#pragma unroll
    for (int kc = 0; kc < 4; kc++) {
        int row = wid * 16 + (lane & 7) + ((lane >> 3) & 1) * 8;
        int col = kc * 16 + ((lane >> 4) & 1) * 8;
        ldmx4(aQ[kc], qsa + (uint32_t)(row * KPQ + col) * 2);
    }

    float m0 = -1e30f, m1 = -1e30f, l0 = 0.f, l1 = 0.f;
    float oacc[8][4];
#pragma unroll
    for (int i = 0; i < 8; i++)
#pragma unroll
        for (int j = 0; j < 4; j++) oacc[i][j] = 0.f;

    const int rg0 = qt * 128 + wid * 16 + (lane >> 2);
    const int rg1 = rg0 + 8;

    for (int kt = 0; kt <= qt; kt++) {
        const int cur = kt & 1;
        if (kt < qt) {
            const __nv_bfloat16* Kn = Kg + (size_t)(kt + 1) * 128 * QKVDIM;
            const __nv_bfloat16* Vn = Vg + (kt + 1) * 128;
#pragma unroll
            for (int it = 0; it < 4; it++) {
                int idx = tid + it * 256, row = idx >> 3, u = idx & 7;
                cp16(ksa[cur ^ 1] + (uint32_t)(row * KPQ + u * 8) * 2, Kn + (size_t)row * QKVDIM + u * 8);
            }
#pragma unroll
            for (int it = 0; it < 4; it++) {
                int idx = tid + it * 256, row = idx >> 4, u = idx & 15;
                cp16(vsa[cur ^ 1] + (uint32_t)(row * KPV + u * 8) * 2, Vn + (size_t)row * SEQ + u * 8);
            }
            CP_COMMIT;
        }

        float sacc[16][4];
#pragma unroll
        for (int i = 0; i < 16; i++)
#pragma unroll
            for (int j = 0; j < 4; j++) sacc[i][j] = 0.f;
#pragma unroll
        for (int kc = 0; kc < 4; kc++) {
#pragma unroll
            for (int nb = 0; nb < 8; nb++) {
                uint32_t r[4];
                int row = nb * 16 + (lane & 7) + ((lane >> 4) & 1) * 8;
                int col = kc * 16 + ((lane >> 3) & 1) * 8;
                ldmx4(r, ksa[cur] + (uint32_t)(row * KPQ + col) * 2);
                mma16816(sacc[2 * nb], aQ[kc], r);
                mma16816(sacc[2 * nb + 1], aQ[kc], r + 2);
            }
        }

        float mx0 = -1e30f, mx1 = -1e30f;
        const int cb = kt * 128 + (lane & 3) * 2;
#pragma unroll
        for (int nt = 0; nt < 16; nt++) {
            int c0 = cb + nt * 8, c1 = c0 + 1;
            float a0 = slope * (float)c0, a1 = slope * (float)c1;
            float s0 = (c0 <= rg0) ? fmaf(sacc[nt][0], 0.125f, a0) : -1e30f;
            float s1 = (c1 <= rg0) ? fmaf(sacc[nt][1], 0.125f, a1) : -1e30f;
            float s2 = (c0 <= rg1) ? fmaf(sacc[nt][2], 0.125f, a0) : -1e30f;
            float s3 = (c1 <= rg1) ? fmaf(sacc[nt][3], 0.125f, a1) : -1e30f;
            sacc[nt][0] = s0; sacc[nt][1] = s1; sacc[nt][2] = s2; sacc[nt][3] = s3;
            mx0 = fmaxf(mx0, fmaxf(s0, s1)); mx1 = fmaxf(mx1, fmaxf(s2, s3));
        }
        mx0 = fmaxf(mx0, __shfl_xor_sync(0xffffffffu, mx0, 1));
        mx0 = fmaxf(mx0, __shfl_xor_sync(0xffffffffu, mx0, 2));
        mx1 = fmaxf(mx1, __shfl_xor_sync(0xffffffffu, mx1, 1));
        mx1 = fmaxf(mx1, __shfl_xor_sync(0xffffffffu, mx1, 2));

        const float mn0 = fmaxf(m0, mx0), mn1 = fmaxf(m1, mx1);
        const float sc0 = __expf(m0 - mn0), sc1 = __expf(m1 - mn1);
        float rs0 = 0.f, rs1 = 0.f;
#pragma unroll
        for (int nt = 0; nt < 16; nt++) {
            float p0 = __expf(sacc[nt][0] - mn0), p1 = __expf(sacc[nt][1] - mn0);
            float p2 = __expf(sacc[nt][2] - mn1), p3 = __expf(sacc[nt][3] - mn1);
            sacc[nt][0] = p0; sacc[nt][1] = p1; sacc[nt][2] = p2; sacc[nt][3] = p3;
            rs0 += p0 + p1; rs1 += p2 + p3;
        }
        rs0 += __shfl_xor_sync(0xffffffffu, rs0, 1);
        rs0 += __shfl_xor_sync(0xffffffffu, rs0, 2);
        rs1 += __shfl_xor_sync(0xffffffffu, rs1, 1);
        rs1 += __shfl_xor_sync(0xffffffffu, rs1, 2);
        l0 = l0 * sc0 + rs0; l1 = l1 * sc1 + rs1;
        m0 = mn0; m1 = mn1;
#pragma unroll
        for (int nt = 0; nt < 8; nt++) {
            oacc[nt][0] *= sc0; oacc[nt][1] *= sc0;
            oacc[nt][2] *= sc1; oacc[nt][3] *= sc1;
        }

#pragma unroll
        for (int kc2 = 0; kc2 < 8; kc2++) {
            uint32_t pa[4] = {
                pack_bf2(sacc[2 * kc2][0],     sacc[2 * kc2][1]),
                pack_bf2(sacc[2 * kc2][2],     sacc[2 * kc2][3]),
                pack_bf2(sacc[2 * kc2 + 1][0], sacc[2 * kc2 + 1][1]),
                pack_bf2(sacc[2 * kc2 + 1][2], sacc[2 * kc2 + 1][3]) };
#pragma unroll
            for (int nb = 0; nb < 4; nb++) {
                uint32_t r[4];
                int row = nb * 16 + (lane & 7) + ((lane >> 4) & 1) * 8;
                int col = kc2 * 16 + ((lane >> 3) & 1) * 8;
                ldmx4(r, vsa[cur] + (uint32_t)(row * KPV + col) * 2);
                mma16816(oacc[2 * nb], pa, r);
                mma16816(oacc[2 * nb + 1], pa, r + 2);
            }
        }

        if (kt < qt) CP_WAIT0;
        __syncthreads();
    }

    const float inv0 = 1.0f / l0, inv1 = 1.0f / l1;
    const int tok0 = b * SEQ + qt * 128 + wid * 16 + (lane >> 2);
#pragma unroll
    for (int nt = 0; nt < 8; nt++) {
        int c = h * DHEAD + nt * 8 + (lane & 3) * 2;
        *(uint32_t*)(ctx + (size_t)tok0 * HID + c) = pack_bf2(oacc[nt][0] * inv0, oacc[nt][1] * inv0);
        *(uint32_t*)(ctx + (size_t)(tok0 + 8) * HID + c) = pack_bf2(oacc[nt][2] * inv1, oacc[nt][3] * inv1);
    }
}

// ---------------- bf16 NT GEMM: 256 threads, warp tile 32x64, K-chunk 32, 3-stage ----
// (exact R5 mainloop — the 1028us configuration)
// EPI: 0 = bias -> bf16, 1 = bias+gelu -> bf16, 2 = bias+residual -> fp32
#define STG_B (128 * KPAD * 2)   // bytes per stage per operand (10240)

template<int EPI>
__global__ __launch_bounds__(256, 2)
void mm_gemm(const __nv_bfloat16* __restrict__ A, int lda,
             const __nv_bfloat16* __restrict__ B, int ldb,
             const float* __restrict__ bias, const float* __restrict__ res,
             void* __restrict__ Cout, int ldc, int K)
{
    extern __shared__ __nv_bfloat16 smbuf[];
    const uint32_t as0 = smem_u32(smbuf);
    const uint32_t bs0 = as0 + 3 * STG_B;
    const int tid = threadIdx.x, wid = tid >> 5, lane = tid & 31;
    const int wm = wid & 3, wn = wid >> 2;
    const int rowB = blockIdx.y * 128, colB = blockIdx.x * 128;
    const __nv_bfloat16* Ag = A + (size_t)rowB * lda;
    const __nv_bfloat16* Bg = B + (size_t)colB * ldb;

    float acc[2][8][4];
#pragma unroll
    for (int i = 0; i < 2; i++)
#pragma unroll
        for (int j = 0; j < 8; j++)
#pragma unroll
            for (int k = 0; k < 4; k++) acc[i][j][k] = 0.f;

    const int NCH = K >> 5;
    cp_chunk(as0, Ag, lda, tid); cp_chunk(bs0, Bg, ldb, tid); CP_COMMIT;
    cp_chunk(as0 + STG_B, Ag + 32, lda, tid); cp_chunk(bs0 + STG_B, Bg + 32, ldb, tid); CP_COMMIT;

    for (int kc = 0; kc < NCH; kc++) {
        if (kc == NCH - 1) { CP_WAIT0; } else { CP_WAIT1; }
        __syncthreads();
        if (kc + 2 < NCH) {
            int st = (kc + 2) % 3;
            cp_chunk(as0 + st * STG_B, Ag + (kc + 2) * 32, lda, tid);
            cp_chunk(bs0 + st * STG_B, Bg + (kc + 2) * 32, ldb, tid);
            CP_COMMIT;
        }
        int st = kc % 3;
        mma_chunk(acc, as0 + st * STG_B, bs0 + st * STG_B, wm, wn, lane);
    }

#pragma unroll
    for (int mt = 0; mt < 2; mt++) {
#pragma unroll
        for (int nt = 0; nt < 8; nt++) {
            const float* ac = acc[mt][nt];
            const int r0 = rowB + wm * 32 + mt * 16 + (lane >> 2);
            const int c = colB + wn * 64 + nt * 8 + (lane & 3) * 2;
            const float b0 = bias[c], b1 = bias[c + 1];
            if (EPI == 2) {
                float* C = (float*)Cout;
                float2 ra = *(const float2*)(res + (size_t)r0 * ldc + c);
                float2 rb = *(const float2*)(res + (size_t)(r0 + 8) * ldc + c);
                float2 o0 = { ac[0] + b0 + ra.x, ac[1] + b1 + ra.y };
                float2 o1 = { ac[2] + b0 + rb.x, ac[3] + b1 + rb.y };
                *(float2*)(C + (size_t)r0 * ldc + c) = o0;
                *(float2*)(C + (size_t)(r0 + 8) * ldc + c) = o1;
            } else {
                __nv_bfloat16* C = (__nv_bfloat16*)Cout;
                float v0 = ac[0] + b0, v1 = ac[1] + b1;
                float v2 = ac[2] + b0, v3 = ac[3] + b1;
                if (EPI == 1) { v0 = gelu_f(v0); v1 = gelu_f(v1); v2 = gelu_f(v2); v3 = gelu_f(v3); }
                *(uint32_t*)(C + (size_t)r0 * ldc + c) = pack_bf2(v0, v1);
                *(uint32_t*)(C + (size_t)(r0 + 8) * ldc + c) = pack_bf2(v2, v3);
            }
        }
    }
}

// ---------------- launch ----------------
extern "C" void kernel_launch(void* const* d_in, const int* in_sizes, int n_in,
                              void* d_out, int out_size)
{
    (void)in_sizes; (void)n_in; (void)out_size;
    const float* hidden  = (const float*)d_in[0];
    const float* alibi   = (const float*)d_in[1];
    const float* qkv_w   = (const float*)d_in[2];
    const float* qkv_b   = (const float*)d_in[3];
    const float* dense_w = (const float*)d_in[4];
    const float* dense_b = (const float*)d_in[5];
    const float* w1      = (const float*)d_in[6];
    const float* b1      = (const float*)d_in[7];
    const float* w2      = (const float*)d_in[8];
    const float* b2      = (const float*)d_in[9];
    const float* ln1w    = (const float*)d_in[10];
    const float* ln1b    = (const float*)d_in[11];
    const float* ln2w    = (const float*)d_in[12];
    const float* ln2b    = (const float*)d_in[13];
    float* x = (float*)d_out;

    __nv_bfloat16 *ph, *pqkv, *pvt, *pctx, *pff, *pwq, *pwd, *pw1, *pw2;
    cudaGetSymbolAddress((void**)&ph,   g_h);
    cudaGetSymbolAddress((void**)&pqkv, g_qkv);
    cudaGetSymbolAddress((void**)&pvt,  g_vt);
    cudaGetSymbolAddress((void**)&pctx, g_ctx);
    cudaGetSymbolAddress((void**)&pff,  g_ff);
    cudaGetSymbolAddress((void**)&pwq,  g_wq);
    cudaGetSymbolAddress((void**)&pwd,  g_wd);
    cudaGetSymbolAddress((void**)&pw1,  g_w1);
    cudaGetSymbolAddress((void**)&pw2,  g_w2);

    const int GEMM_SMEM  = 6 * STG_B;                                  // 61440
    const int FLASH_SMEM = (3 * 128 * KPQ + 2 * 64 * KPV) * 2;         // 90112
    cudaFuncSetAttribute(mm_gemm<0>, cudaFuncAttributeMaxDynamicSharedMemorySize, GEMM_SMEM);
    cudaFuncSetAttribute(mm_gemm<1>, cudaFuncAttributeMaxDynamicSharedMemorySize, GEMM_SMEM);
    cudaFuncSetAttribute(mm_gemm<2>, cudaFuncAttributeMaxDynamicSharedMemorySize, GEMM_SMEM);
    cudaFuncSetAttribute(flash_kernel, cudaFuncAttributeMaxDynamicSharedMemorySize, FLASH_SMEM);

    cudaMemcpyAsync(x, hidden, sizeof(float) * (size_t)NTOK * HID, cudaMemcpyDeviceToDevice);

    // weights -> bf16 (all 4 arrays in one launch)
    const int nq = NLAYER * QKVDIM * HID / 4, nd = NLAYER * HID * HID / 4;
    const int n1 = NLAYER * FFDIM * HID / 4, n2 = NLAYER * HID * FFDIM / 4;
    int nmax = n1 > nq ? n1 : nq;
    cvt4_kernel<<<dim3((nmax + 255) / 256, 4), 256>>>(
        qkv_w, pwq, nq, dense_w, pwd, nd, w1, pw1, n1, w2, pw2, n2);

    for (int l = 0; l < NLAYER; l++) {
        // --- attention ---
        ln_kernel<<<NTOK, 256>>>(x, ln1w + l * HID, ln1b + l * HID, ph);
        mm_gemm<0><<<dim3(QKVDIM / 128, NTOK / 128), 256, GEMM_SMEM>>>(
            ph, HID, pwq + (size_t)l * QKVDIM * HID, HID,
            qkv_b + (size_t)l * QKVDIM, nullptr, pqkv, QKVDIM, HID);
        vtrans_kernel<<<dim3(SEQ / 64, 1, BATCH * NHEAD), 256>>>(pqkv, pvt);
        flash_kernel<<<dim3(SEQ / 128, BATCH * NHEAD), 256, FLASH_SMEM>>>(pqkv, pvt, alibi, pctx);
        mm_gemm<2><<<dim3(HID / 128, NTOK / 128), 256, GEMM_SMEM>>>(
            pctx, HID, pwd + (size_t)l * HID * HID, HID,
            dense_b + (size_t)l * HID, x, x, HID, HID);
        // --- MLP ---
        ln_kernel<<<NTOK, 256>>>(x, ln2w + l * HID, ln2b + l * HID, ph);
        mm_gemm<1><<<dim3(FFDIM / 128, NTOK / 128), 256, GEMM_SMEM>>>(
            ph, HID, pw1 + (size_t)l * FFDIM * HID, HID,
            b1 + (size_t)l * FFDIM, nullptr, pff, FFDIM, HID);
        mm_gemm<2><<<dim3(HID / 128, NTOK / 128), 256, GEMM_SMEM>>>(
            pff, FFDIM, pw2 + (size_t)l * HID * FFDIM, FFDIM,
            b2 + (size_t)l * HID, x, x, HID, FFDIM);
    }
}

// round 12
// speedup vs baseline: 1.3609x; 1.0182x over previous
#include <cuda_runtime.h>
#include <cuda_bf16.h>
#include <math.h>
#include <stdint.h>

#define NLAYER 2
#define BATCH  2
#define SEQ    2048
#define HID    1024
#define NHEAD  16
#define DHEAD  64
#define FFDIM  4096
#define NTOK   (BATCH*SEQ)      // 4096
#define QKVDIM (3*HID)          // 3072
#define KPAD   40               // GEMM: 32-elem K chunk padded to 40
#define KPQ    72               // flash: 64-elem rows padded to 72

// ---------------- scratch (device globals) ----------------
__device__ __nv_bfloat16 g_h[NTOK*HID];
__device__ __nv_bfloat16 g_qkv[(size_t)NTOK*QKVDIM];
__device__ __nv_bfloat16 g_ctx[NTOK*HID];
__device__ __nv_bfloat16 g_ff[(size_t)NTOK*FFDIM];
__device__ __nv_bfloat16 g_wq[(size_t)NLAYER*QKVDIM*HID];
__device__ __nv_bfloat16 g_wd[(size_t)NLAYER*HID*HID];
__device__ __nv_bfloat16 g_w1[(size_t)NLAYER*FFDIM*HID];
__device__ __nv_bfloat16 g_w2[(size_t)NLAYER*HID*FFDIM];

// ---------------- helpers ----------------
__device__ __forceinline__ uint32_t smem_u32(const void* p) {
    uint32_t a;
    asm("{ .reg .u64 t; cvta.to.shared.u64 t, %1; cvt.u32.u64 %0, t; }" : "=r"(a) : "l"(p));
    return a;
}
__device__ __forceinline__ void cp16(uint32_t s, const void* g) {
    asm volatile("cp.async.cg.shared.global [%0], [%1], 16;" :: "r"(s), "l"(g));
}
#define CP_COMMIT asm volatile("cp.async.commit_group;")
#define CP_WAIT1  asm volatile("cp.async.wait_group 1;")
#define CP_WAIT0  asm volatile("cp.async.wait_group 0;")

__device__ __forceinline__ void ldmx4(uint32_t* r, uint32_t addr) {
    asm volatile("ldmatrix.sync.aligned.m8n8.x4.shared.b16 {%0,%1,%2,%3}, [%4];"
                 : "=r"(r[0]), "=r"(r[1]), "=r"(r[2]), "=r"(r[3]) : "r"(addr));
}
__device__ __forceinline__ void ldmx4t(uint32_t* r, uint32_t addr) {
    asm volatile("ldmatrix.sync.aligned.m8n8.x4.trans.shared.b16 {%0,%1,%2,%3}, [%4];"
                 : "=r"(r[0]), "=r"(r[1]), "=r"(r[2]), "=r"(r[3]) : "r"(addr));
}
__device__ __forceinline__ void mma16816(float* c, const uint32_t* a, const uint32_t* b) {
    asm volatile("mma.sync.aligned.m16n8k16.row.col.f32.bf16.bf16.f32 "
                 "{%0,%1,%2,%3}, {%4,%5,%6,%7}, {%8,%9}, {%0,%1,%2,%3};"
                 : "+f"(c[0]), "+f"(c[1]), "+f"(c[2]), "+f"(c[3])
                 : "r"(a[0]), "r"(a[1]), "r"(a[2]), "r"(a[3]), "r"(b[0]), "r"(b[1]));
}
__device__ __forceinline__ uint32_t pack_bf2(float a, float b) {
    __nv_bfloat162 h = __floats2bfloat162_rn(a, b);
    return *(uint32_t*)&h;
}
__device__ __forceinline__ float gelu_f(float v) {
    return 0.5f * v * (1.0f + erff(v * 0.70710678118654752440f));
}
__device__ __forceinline__ float warpSum(float v) {
#pragma unroll
    for (int o = 16; o > 0; o >>= 1) v += __shfl_xor_sync(0xffffffffu, v, o);
    return v;
}

// load 128 x 32 bf16 chunk from g (row stride ld elems) into smem (KPAD-elem rows)
__device__ __forceinline__ void cp_chunk(uint32_t sbase, const __nv_bfloat16* g, int ld, int tid) {
#pragma unroll
    for (int it = 0; it < 2; it++) {
        int idx = tid + it * 256;
        int row = idx >> 2, q = idx & 3;
        cp16(sbase + (uint32_t)(row * KPAD + q * 8) * 2, g + (size_t)row * ld + q * 8);
    }
}

// one 32-wide K-chunk of warp-level MMAs (128x128 CTA tile, 4x2 warps, 32x64 warp tile)
__device__ __forceinline__ void mma_chunk(float (&acc)[2][8][4], uint32_t abase, uint32_t bbase,
                                          int wm, int wn, int lane) {
#pragma unroll
    for (int ks = 0; ks < 32; ks += 16) {
        uint32_t a[2][4];
#pragma unroll
        for (int mt = 0; mt < 2; mt++) {
            int row = wm * 32 + mt * 16 + (lane & 7) + ((lane >> 3) & 1) * 8;
            int col = ks + ((lane >> 4) & 1) * 8;
            ldmx4(a[mt], abase + (uint32_t)(row * KPAD + col) * 2);
        }
        uint32_t bf[8][2];
#pragma unroll
        for (int nb = 0; nb < 4; nb++) {
            int row = wn * 64 + nb * 16 + (lane & 7) + ((lane >> 4) & 1) * 8;
            int col = ks + ((lane >> 3) & 1) * 8;
            uint32_t r[4];
            ldmx4(r, bbase + (uint32_t)(row * KPAD + col) * 2);
            bf[2 * nb][0] = r[0]; bf[2 * nb][1] = r[1];
            bf[2 * nb + 1][0] = r[2]; bf[2 * nb + 1][1] = r[3];
        }
#pragma unroll
        for (int mt = 0; mt < 2; mt++)
#pragma unroll
            for (int nt = 0; nt < 8; nt++)
                mma16816(acc[mt][nt], a[mt], bf[nt]);
    }
}

// ---------------- LayerNorm (fp32 in, bf16 out) ----------------
__global__ __launch_bounds__(256)
void ln_kernel(const float* __restrict__ x, const float* __restrict__ w,
               const float* __restrict__ b, __nv_bfloat16* __restrict__ out)
{
    __shared__ float sh[8];
    __shared__ float stat;
    const int t = blockIdx.x;
    const float* xr = x + (size_t)t * HID;
    const int lane = threadIdx.x & 31, wp = threadIdx.x >> 5;

    float v[4];
    float s = 0.f;
#pragma unroll
    for (int i = 0; i < 4; i++) { v[i] = xr[threadIdx.x + i * 256]; s += v[i]; }
    s = warpSum(s);
    if (lane == 0) sh[wp] = s;
    __syncthreads();
    if (threadIdx.x == 0) {
        float r = 0.f;
#pragma unroll
        for (int i = 0; i < 8; i++) r += sh[i];
        stat = r * (1.0f / HID);
    }
    __syncthreads();
    const float mu = stat;

    float s2 = 0.f;
#pragma unroll
    for (int i = 0; i < 4; i++) { float d = v[i] - mu; s2 += d * d; }
    s2 = warpSum(s2);
    __syncthreads();
    if (lane == 0) sh[wp] = s2;
    __syncthreads();
    if (threadIdx.x == 0) {
        float r = 0.f;
#pragma unroll
        for (int i = 0; i < 8; i++) r += sh[i];
        stat = rsqrtf(r * (1.0f / HID) + 1e-5f);
    }
    __syncthreads();
    const float rs = stat;

    __nv_bfloat16* orow = out + (size_t)t * HID;
#pragma unroll
    for (int i = 0; i < 4; i++) {
        int c = threadIdx.x + i * 256;
        orow[c] = __float2bfloat16((v[i] - mu) * rs * w[c] + b[c]);
    }
}

// ---------------- merged weight convert fp32 -> bf16 (4 arrays via grid.y) ----------
__global__ __launch_bounds__(256)
void cvt4_kernel(const float* __restrict__ s0, __nv_bfloat16* __restrict__ d0, int n0,
                 const float* __restrict__ s1, __nv_bfloat16* __restrict__ d1, int n1,
                 const float* __restrict__ s2, __nv_bfloat16* __restrict__ d2, int n2,
                 const float* __restrict__ s3, __nv_bfloat16* __restrict__ d3, int n3)
{
    const float* src; __nv_bfloat16* dst; int n;
    switch (blockIdx.y) {
        case 0: src = s0; dst = d0; n = n0; break;
        case 1: src = s1; dst = d1; n = n1; break;
        case 2: src = s2; dst = d2; n = n2; break;
        default: src = s3; dst = d3; n = n3; break;
    }
    int i = blockIdx.x * 256 + threadIdx.x;
    if (i < n) {
        float4 v = ((const float4*)src)[i];
        uint2 o;
        o.x = pack_bf2(v.x, v.y);
        o.y = pack_bf2(v.z, v.w);
        ((uint2*)dst)[i] = o;
    }
}

// ---------------- flash attention: ctx = softmax(QK^T/8 + alibi, causal) V ----------
// grid (16 qtiles [reversed], B*NH). 8 warps, each owns 16 q-rows x full 128 k-tile.
// V kept row-major [kv, d] in smem; B fragments via ldmatrix.trans (no vtrans stage).
__global__ __launch_bounds__(256)
void flash_kernel(const __nv_bfloat16* __restrict__ qkv,
                  const float* __restrict__ alibi,
                  __nv_bfloat16* __restrict__ ctx)
{
    extern __shared__ __nv_bfloat16 sm[];
    const int tid = threadIdx.x, wid = tid >> 5, lane = tid & 31;
    const int qt = (int)gridDim.x - 1 - (int)blockIdx.x;   // big tiles first
    const int z = blockIdx.y, b = z >> 4, h = z & 15;

    const uint32_t qsa = smem_u32(sm);                              // Q: 128 x KPQ
    const uint32_t ksa[2] = { qsa + 128 * KPQ * 2, qsa + 2 * 128 * KPQ * 2 };
    const uint32_t vsa[2] = { qsa + 3 * 128 * KPQ * 2, qsa + 4 * 128 * KPQ * 2 };

    const __nv_bfloat16* Qg = qkv + ((size_t)(b * SEQ) + qt * 128) * QKVDIM + h * DHEAD;
    const __nv_bfloat16* Kg = qkv + (size_t)(b * SEQ) * QKVDIM + HID + h * DHEAD;
    const __nv_bfloat16* Vg = qkv + (size_t)(b * SEQ) * QKVDIM + 2 * HID + h * DHEAD;
    const float slope = alibi[(size_t)z * SEQ + 1];   // alibi[...,c] == slope*c exactly

    {
#pragma unroll
        for (int it = 0; it < 4; it++) {
            int idx = tid + it * 256, row = idx >> 3, u = idx & 7;
            cp16(qsa + (uint32_t)(row * KPQ + u * 8) * 2, Qg + (size_t)row * QKVDIM + u * 8);
        }
#pragma unroll
        for (int it = 0; it < 4; it++) {
            int idx = tid + it * 256, row = idx >> 3, u = idx & 7;
            cp16(ksa[0] + (uint32_t)(row * KPQ + u * 8) * 2, Kg + (size_t)row * QKVDIM + u * 8);
        }
#pragma unroll
        for (int it = 0; it < 4; it++) {
            int idx = tid + it * 256, row = idx >> 3, u = idx & 7;
            cp16(vsa[0] + (uint32_t)(row * KPQ + u * 8) * 2, Vg + (size_t)row * QKVDIM + u * 8);
        }
        CP_COMMIT;
    }
    CP_WAIT0;
    __syncthreads();

    uint32_t aQ[4][4];
#pragma unroll
    for (int kc = 0; kc < 4; kc++) {
        int row = wid * 16 + (lane & 7) + ((lane >> 3) & 1) * 8;
        int col = kc * 16 + ((lane >> 4) & 1) * 8;
        ldmx4(aQ[kc], qsa + (uint32_t)(row * KPQ + col) * 2);
    }

    float m0 = -1e30f, m1 = -1e30f, l0 = 0.f, l1 = 0.f;
    float oacc[8][4];
#pragma unroll
    for (int i = 0; i < 8; i++)
#pragma unroll
        for (int j = 0; j < 4; j++) oacc[i][j] = 0.f;

    const int rg0 = qt * 128 + wid * 16 + (lane >> 2);
    const int rg1 = rg0 + 8;

    for (int kt = 0; kt <= qt; kt++) {
        const int cur = kt & 1;
        if (kt < qt) {
            const __nv_bfloat16* Kn = Kg + (size_t)(kt + 1) * 128 * QKVDIM;
            const __nv_bfloat16* Vn = Vg + (size_t)(kt + 1) * 128 * QKVDIM;
#pragma unroll
            for (int it = 0; it < 4; it++) {
                int idx = tid + it * 256, row = idx >> 3, u = idx & 7;
                cp16(ksa[cur ^ 1] + (uint32_t)(row * KPQ + u * 8) * 2, Kn + (size_t)row * QKVDIM + u * 8);
            }
#pragma unroll
            for (int it = 0; it < 4; it++) {
                int idx = tid + it * 256, row = idx >> 3, u = idx & 7;
                cp16(vsa[cur ^ 1] + (uint32_t)(row * KPQ + u * 8) * 2, Vn + (size_t)row * QKVDIM + u * 8);
            }
            CP_COMMIT;
        }

        float sacc[16][4];
#pragma unroll
        for (int i = 0; i < 16; i++)
#pragma unroll
            for (int j = 0; j < 4; j++) sacc[i][j] = 0.f;
#pragma unroll
        for (int kc = 0; kc < 4; kc++) {
#pragma unroll
            for (int nb = 0; nb < 8; nb++) {
                uint32_t r[4];
                int row = nb * 16 + (lane & 7) + ((lane >> 4) & 1) * 8;
                int col = kc * 16 + ((lane >> 3) & 1) * 8;
                ldmx4(r, ksa[cur] + (uint32_t)(row * KPQ + col) * 2);
                mma16816(sacc[2 * nb], aQ[kc], r);
                mma16816(sacc[2 * nb + 1], aQ[kc], r + 2);
            }
        }

        float mx0 = -1e30f, mx1 = -1e30f;
        const int cb = kt * 128 + (lane & 3) * 2;
#pragma unroll
        for (int nt = 0; nt < 16; nt++) {
            int c0 = cb + nt * 8, c1 = c0 + 1;
            float a0 = slope * (float)c0, a1 = slope * (float)c1;
            float s0 = (c0 <= rg0) ? fmaf(sacc[nt][0], 0.125f, a0) : -1e30f;
            float s1 = (c1 <= rg0) ? fmaf(sacc[nt][1], 0.125f, a1) : -1e30f;
            float s2 = (c0 <= rg1) ? fmaf(sacc[nt][2], 0.125f, a0) : -1e30f;
            float s3 = (c1 <= rg1) ? fmaf(sacc[nt][3], 0.125f, a1) : -1e30f;
            sacc[nt][0] = s0; sacc[nt][1] = s1; sacc[nt][2] = s2; sacc[nt][3] = s3;
            mx0 = fmaxf(mx0, fmaxf(s0, s1)); mx1 = fmaxf(mx1, fmaxf(s2, s3));
        }
        mx0 = fmaxf(mx0, __shfl_xor_sync(0xffffffffu, mx0, 1));
        mx0 = fmaxf(mx0, __shfl_xor_sync(0xffffffffu, mx0, 2));
        mx1 = fmaxf(mx1, __shfl_xor_sync(0xffffffffu, mx1, 1));
        mx1 = fmaxf(mx1, __shfl_xor_sync(0xffffffffu, mx1, 2));

        const float mn0 = fmaxf(m0, mx0), mn1 = fmaxf(m1, mx1);
        const float sc0 = __expf(m0 - mn0), sc1 = __expf(m1 - mn1);
        float rs0 = 0.f, rs1 = 0.f;
#pragma unroll
        for (int nt = 0; nt < 16; nt++) {
            float p0 = __expf(sacc[nt][0] - mn0), p1 = __expf(sacc[nt][1] - mn0);
            float p2 = __expf(sacc[nt][2] - mn1), p3 = __expf(sacc[nt][3] - mn1);
            sacc[nt][0] = p0; sacc[nt][1] = p1; sacc[nt][2] = p2; sacc[nt][3] = p3;
            rs0 += p0 + p1; rs1 += p2 + p3;
        }
        rs0 += __shfl_xor_sync(0xffffffffu, rs0, 1);
        rs0 += __shfl_xor_sync(0xffffffffu, rs0, 2);
        rs1 += __shfl_xor_sync(0xffffffffu, rs1, 1);
        rs1 += __shfl_xor_sync(0xffffffffu, rs1, 2);
        l0 = l0 * sc0 + rs0; l1 = l1 * sc1 + rs1;
        m0 = mn0; m1 = mn1;
#pragma unroll
        for (int nt = 0; nt < 8; nt++) {
            oacc[nt][0] *= sc0; oacc[nt][1] *= sc0;
            oacc[nt][2] *= sc1; oacc[nt][3] *= sc1;
        }

        // O += P V : B fragments trans-loaded from row-major V [kv, d]
#pragma unroll
        for (int kc2 = 0; kc2 < 8; kc2++) {
            uint32_t pa[4] = {
                pack_bf2(sacc[2 * kc2][0],     sacc[2 * kc2][1]),
                pack_bf2(sacc[2 * kc2][2],     sacc[2 * kc2][3]),
                pack_bf2(sacc[2 * kc2 + 1][0], sacc[2 * kc2 + 1][1]),
                pack_bf2(sacc[2 * kc2 + 1][2], sacc[2 * kc2 + 1][3]) };
#pragma unroll
            for (int nb = 0; nb < 4; nb++) {
                uint32_t r[4];
                int row = kc2 * 16 + (lane & 7) + ((lane >> 3) & 1) * 8;   // kv
                int col = nb * 16 + ((lane >> 4) & 1) * 8;                  // d
                ldmx4t(r, vsa[cur] + (uint32_t)(row * KPQ + col) * 2);
                mma16816(oacc[2 * nb], pa, r);
                mma16816(oacc[2 * nb + 1], pa, r + 2);
            }
        }

        if (kt < qt) CP_WAIT0;
        __syncthreads();
    }

    const float inv0 = 1.0f / l0, inv1 = 1.0f / l1;
    const int tok0 = b * SEQ + qt * 128 + wid * 16 + (lane >> 2);
#pragma unroll
    for (int nt = 0; nt < 8; nt++) {
        int c = h * DHEAD + nt * 8 + (lane & 3) * 2;
        *(uint32_t*)(ctx + (size_t)tok0 * HID + c) = pack_bf2(oacc[nt][0] * inv0, oacc[nt][1] * inv0);
        *(uint32_t*)(ctx + (size_t)(tok0 + 8) * HID + c) = pack_bf2(oacc[nt][2] * inv1, oacc[nt][3] * inv1);
    }
}

// ---------------- bf16 NT GEMM: 256 threads, warp tile 32x64, K-chunk 32, 3-stage ----
// EPI: 0 = bias -> bf16, 1 = bias+gelu -> bf16, 2 = bias+residual -> fp32
#define STG_B (128 * KPAD * 2)   // bytes per stage per operand (10240)

template<int EPI>
__global__ __launch_bounds__(256, 2)
void mm_gemm(const __nv_bfloat16* __restrict__ A, int lda,
             const __nv_bfloat16* __restrict__ B, int ldb,
             const float* __restrict__ bias, const float* __restrict__ res,
             void* __restrict__ Cout, int ldc, int K)
{
    extern __shared__ __nv_bfloat16 smbuf[];
    const uint32_t as0 = smem_u32(smbuf);
    const uint32_t bs0 = as0 + 3 * STG_B;
    const int tid = threadIdx.x, wid = tid >> 5, lane = tid & 31;
    const int wm = wid & 3, wn = wid >> 2;
    const int rowB = blockIdx.y * 128, colB = blockIdx.x * 128;
    const __nv_bfloat16* Ag = A + (size_t)rowB * lda;
    const __nv_bfloat16* Bg = B + (size_t)colB * ldb;

    float acc[2][8][4];
#pragma unroll
    for (int i = 0; i < 2; i++)
#pragma unroll
        for (int j = 0; j < 8; j++)
#pragma unroll
            for (int k = 0; k < 4; k++) acc[i][j][k] = 0.f;

    const int NCH = K >> 5;
    cp_chunk(as0, Ag, lda, tid); cp_chunk(bs0, Bg, ldb, tid); CP_COMMIT;
    cp_chunk(as0 + STG_B, Ag + 32, lda, tid); cp_chunk(bs0 + STG_B, Bg + 32, ldb, tid); CP_COMMIT;

    for (int kc = 0; kc < NCH; kc++) {
        if (kc == NCH - 1) { CP_WAIT0; } else { CP_WAIT1; }
        __syncthreads();
        if (kc + 2 < NCH) {
            int st = (kc + 2) % 3;
            cp_chunk(as0 + st * STG_B, Ag + (kc + 2) * 32, lda, tid);
            cp_chunk(bs0 + st * STG_B, Bg + (kc + 2) * 32, ldb, tid);
            CP_COMMIT;
        }
        int st = kc % 3;
        mma_chunk(acc, as0 + st * STG_B, bs0 + st * STG_B, wm, wn, lane);
    }

#pragma unroll
    for (int mt = 0; mt < 2; mt++) {
#pragma unroll
        for (int nt = 0; nt < 8; nt++) {
            const float* ac = acc[mt][nt];
            const int r0 = rowB + wm * 32 + mt * 16 + (lane >> 2);
            const int c = colB + wn * 64 + nt * 8 + (lane & 3) * 2;
            const float b0 = bias[c], b1 = bias[c + 1];
            if (EPI == 2) {
                float* C = (float*)Cout;
                float2 ra = *(const float2*)(res + (size_t)r0 * ldc + c);
                float2 rb = *(const float2*)(res + (size_t)(r0 + 8) * ldc + c);
                float2 o0 = { ac[0] + b0 + ra.x, ac[1] + b1 + ra.y };
                float2 o1 = { ac[2] + b0 + rb.x, ac[3] + b1 + rb.y };
                *(float2*)(C + (size_t)r0 * ldc + c) = o0;
                *(float2*)(C + (size_t)(r0 + 8) * ldc + c) = o1;
            } else {
                __nv_bfloat16* C = (__nv_bfloat16*)Cout;
                float v0 = ac[0] + b0, v1 = ac[1] + b1;
                float v2 = ac[2] + b0, v3 = ac[3] + b1;
                if (EPI == 1) { v0 = gelu_f(v0); v1 = gelu_f(v1); v2 = gelu_f(v2); v3 = gelu_f(v3); }
                *(uint32_t*)(C + (size_t)r0 * ldc + c) = pack_bf2(v0, v1);
                *(uint32_t*)(C + (size_t)(r0 + 8) * ldc + c) = pack_bf2(v2, v3);
            }
        }
    }
}

// ---------------- launch ----------------
extern "C" void kernel_launch(void* const* d_in, const int* in_sizes, int n_in,
                              void* d_out, int out_size)
{
    (void)in_sizes; (void)n_in; (void)out_size;
    const float* hidden  = (const float*)d_in[0];
    const float* alibi   = (const float*)d_in[1];
    const float* qkv_w   = (const float*)d_in[2];
    const float* qkv_b   = (const float*)d_in[3];
    const float* dense_w = (const float*)d_in[4];
    const float* dense_b = (const float*)d_in[5];
    const float* w1      = (const float*)d_in[6];
    const float* b1      = (const float*)d_in[7];
    const float* w2      = (const float*)d_in[8];
    const float* b2      = (const float*)d_in[9];
    const float* ln1w    = (const float*)d_in[10];
    const float* ln1b    = (const float*)d_in[11];
    const float* ln2w    = (const float*)d_in[12];
    const float* ln2b    = (const float*)d_in[13];
    float* x = (float*)d_out;

    __nv_bfloat16 *ph, *pqkv, *pctx, *pff, *pwq, *pwd, *pw1, *pw2;
    cudaGetSymbolAddress((void**)&ph,   g_h);
    cudaGetSymbolAddress((void**)&pqkv, g_qkv);
    cudaGetSymbolAddress((void**)&pctx, g_ctx);
    cudaGetSymbolAddress((void**)&pff,  g_ff);
    cudaGetSymbolAddress((void**)&pwq,  g_wq);
    cudaGetSymbolAddress((void**)&pwd,  g_wd);
    cudaGetSymbolAddress((void**)&pw1,  g_w1);
    cudaGetSymbolAddress((void**)&pw2,  g_w2);

    const int GEMM_SMEM  = 6 * STG_B;                // 61440
    const int FLASH_SMEM = 5 * 128 * KPQ * 2;        // 92160
    cudaFuncSetAttribute(mm_gemm<0>, cudaFuncAttributeMaxDynamicSharedMemorySize, GEMM_SMEM);
    cudaFuncSetAttribute(mm_gemm<1>, cudaFuncAttributeMaxDynamicSharedMemorySize, GEMM_SMEM);
    cudaFuncSetAttribute(mm_gemm<2>, cudaFuncAttributeMaxDynamicSharedMemorySize, GEMM_SMEM);
    cudaFuncSetAttribute(flash_kernel, cudaFuncAttributeMaxDynamicSharedMemorySize, FLASH_SMEM);

    cudaMemcpyAsync(x, hidden, sizeof(float) * (size_t)NTOK * HID, cudaMemcpyDeviceToDevice);

    // weights -> bf16 (all 4 arrays in one launch)
    const int nq = NLAYER * QKVDIM * HID / 4, nd = NLAYER * HID * HID / 4;
    const int n1 = NLAYER * FFDIM * HID / 4, n2 = NLAYER * HID * FFDIM / 4;
    int nmax = n1 > nq ? n1 : nq;
    cvt4_kernel<<<dim3((nmax + 255) / 256, 4), 256>>>(
        qkv_w, pwq, nq, dense_w, pwd, nd, w1, pw1, n1, w2, pw2, n2);

    for (int l = 0; l < NLAYER; l++) {
        // --- attention ---
        ln_kernel<<<NTOK, 256>>>(x, ln1w + l * HID, ln1b + l * HID, ph);
        mm_gemm<0><<<dim3(QKVDIM / 128, NTOK / 128), 256, GEMM_SMEM>>>(
            ph, HID, pwq + (size_t)l * QKVDIM * HID, HID,
            qkv_b + (size_t)l * QKVDIM, nullptr, pqkv, QKVDIM, HID);
        flash_kernel<<<dim3(SEQ / 128, BATCH * NHEAD), 256, FLASH_SMEM>>>(pqkv, alibi, pctx);
        mm_gemm<2><<<dim3(HID / 128, NTOK / 128), 256, GEMM_SMEM>>>(
            pctx, HID, pwd + (size_t)l * HID * HID, HID,
            dense_b + (size_t)l * HID, x, x, HID, HID);
        // --- MLP ---
        ln_kernel<<<NTOK, 256>>>(x, ln2w + l * HID, ln2b + l * HID, ph);
        mm_gemm<1><<<dim3(FFDIM / 128, NTOK / 128), 256, GEMM_SMEM>>>(
            ph, HID, pw1 + (size_t)l * FFDIM * HID, HID,
            b1 + (size_t)l * FFDIM, nullptr, pff, FFDIM, HID);
        mm_gemm<2><<<dim3(HID / 128, NTOK / 128), 256, GEMM_SMEM>>>(
            pff, FFDIM, pw2 + (size_t)l * HID * FFDIM, FFDIM,
            b2 + (size_t)l * HID, x, x, HID, FFDIM);
    }
}

// round 14
// speedup vs baseline: 1.3843x; 1.0172x over previous
#include <cuda_runtime.h>
#include <cuda_bf16.h>
#include <math.h>
#include <stdint.h>

#define NLAYER 2
#define BATCH  2
#define SEQ    2048
#define HID    1024
#define NHEAD  16
#define DHEAD  64
#define FFDIM  4096
#define NTOK   (BATCH*SEQ)      // 4096
#define QKVDIM (3*HID)          // 3072
#define KPAD   40               // GEMM: 32-elem K chunk padded to 40
#define KPQ    72               // flash: 64-elem rows padded to 72

// ---------------- scratch (device globals) ----------------
__device__ __nv_bfloat16 g_h[NTOK*HID];
__device__ __nv_bfloat16 g_qkv[(size_t)NTOK*QKVDIM];
__device__ __nv_bfloat16 g_ctx[NTOK*HID];
__device__ __nv_bfloat16 g_ff[(size_t)NTOK*FFDIM];
__device__ __nv_bfloat16 g_wq[(size_t)NLAYER*QKVDIM*HID];
__device__ __nv_bfloat16 g_wd[(size_t)NLAYER*HID*HID];
__device__ __nv_bfloat16 g_w1[(size_t)NLAYER*FFDIM*HID];
__device__ __nv_bfloat16 g_w2[(size_t)NLAYER*HID*FFDIM];

// ---------------- helpers ----------------
__device__ __forceinline__ uint32_t smem_u32(const void* p) {
    uint32_t a;
    asm("{ .reg .u64 t; cvta.to.shared.u64 t, %1; cvt.u32.u64 %0, t; }" : "=r"(a) : "l"(p));
    return a;
}
__device__ __forceinline__ void cp16(uint32_t s, const void* g) {
    asm volatile("cp.async.cg.shared.global [%0], [%1], 16;" :: "r"(s), "l"(g));
}
#define CP_COMMIT asm volatile("cp.async.commit_group;")
#define CP_WAIT1  asm volatile("cp.async.wait_group 1;")
#define CP_WAIT0  asm volatile("cp.async.wait_group 0;")

__device__ __forceinline__ void ldmx4(uint32_t* r, uint32_t addr) {
    asm volatile("ldmatrix.sync.aligned.m8n8.x4.shared.b16 {%0,%1,%2,%3}, [%4];"
                 : "=r"(r[0]), "=r"(r[1]), "=r"(r[2]), "=r"(r[3]) : "r"(addr));
}
__device__ __forceinline__ void ldmx4t(uint32_t* r, uint32_t addr) {
    asm volatile("ldmatrix.sync.aligned.m8n8.x4.trans.shared.b16 {%0,%1,%2,%3}, [%4];"
                 : "=r"(r[0]), "=r"(r[1]), "=r"(r[2]), "=r"(r[3]) : "r"(addr));
}
__device__ __forceinline__ void mma16816(float* c, const uint32_t* a, const uint32_t* b) {
    asm volatile("mma.sync.aligned.m16n8k16.row.col.f32.bf16.bf16.f32 "
                 "{%0,%1,%2,%3}, {%4,%5,%6,%7}, {%8,%9}, {%0,%1,%2,%3};"
                 : "+f"(c[0]), "+f"(c[1]), "+f"(c[2]), "+f"(c[3])
                 : "r"(a[0]), "r"(a[1]), "r"(a[2]), "r"(a[3]), "r"(b[0]), "r"(b[1]));
}
__device__ __forceinline__ uint32_t pack_bf2(float a, float b) {
    __nv_bfloat162 h = __floats2bfloat162_rn(a, b);
    return *(uint32_t*)&h;
}
__device__ __forceinline__ float gelu_f(float v) {
    return 0.5f * v * (1.0f + erff(v * 0.70710678118654752440f));
}
__device__ __forceinline__ float warpSum(float v) {
#pragma unroll
    for (int o = 16; o > 0; o >>= 1) v += __shfl_xor_sync(0xffffffffu, v, o);
    return v;
}

// load 128 x 32 bf16 chunk from g (row stride ld elems) into smem (KPAD-elem rows)
__device__ __forceinline__ void cp_chunk(uint32_t sbase, const __nv_bfloat16* g, int ld, int tid) {
#pragma unroll
    for (int it = 0; it < 2; it++) {
        int idx = tid + it * 256;
        int row = idx >> 2, q = idx & 3;
        cp16(sbase + (uint32_t)(row * KPAD + q * 8) * 2, g + (size_t)row * ld + q * 8);
    }
}

// one 32-wide K-chunk of warp-level MMAs (128x128 CTA tile, 4x2 warps, 32x64 warp tile)
__device__ __forceinline__ void mma_chunk(float (&acc)[2][8][4], uint32_t abase, uint32_t bbase,
                                          int wm, int wn, int lane) {
#pragma unroll
    for (int ks = 0; ks < 32; ks += 16) {
        uint32_t a[2][4];
#pragma unroll
        for (int mt = 0; mt < 2; mt++) {
            int row = wm * 32 + mt * 16 + (lane & 7) + ((lane >> 3) & 1) * 8;
            int col = ks + ((lane >> 4) & 1) * 8;
            ldmx4(a[mt], abase + (uint32_t)(row * KPAD + col) * 2);
        }
        uint32_t bf[8][2];
#pragma unroll
        for (int nb = 0; nb < 4; nb++) {
            int row = wn * 64 + nb * 16 + (lane & 7) + ((lane >> 4) & 1) * 8;
            int col = ks + ((lane >> 3) & 1) * 8;
            uint32_t r[4];
            ldmx4(r, bbase + (uint32_t)(row * KPAD + col) * 2);
            bf[2 * nb][0] = r[0]; bf[2 * nb][1] = r[1];
            bf[2 * nb + 1][0] = r[2]; bf[2 * nb + 1][1] = r[3];
        }
#pragma unroll
        for (int mt = 0; mt < 2; mt++)
#pragma unroll
            for (int nt = 0; nt < 8; nt++)
                mma16816(acc[mt][nt], a[mt], bf[nt]);
    }
}

// ---------------- LayerNorm (fp32 in, bf16 out) ----------------
__global__ __launch_bounds__(256)
void ln_kernel(const float* __restrict__ x, const float* __restrict__ w,
               const float* __restrict__ b, __nv_bfloat16* __restrict__ out)
{
    __shared__ float sh[8];
    __shared__ float stat;
    const int t = blockIdx.x;
    const float* xr = x + (size_t)t * HID;
    const int lane = threadIdx.x & 31, wp = threadIdx.x >> 5;

    float v[4];
    float s = 0.f;
#pragma unroll
    for (int i = 0; i < 4; i++) { v[i] = xr[threadIdx.x + i * 256]; s += v[i]; }
    s = warpSum(s);
    if (lane == 0) sh[wp] = s;
    __syncthreads();
    if (threadIdx.x == 0) {
        float r = 0.f;
#pragma unroll
        for (int i = 0; i < 8; i++) r += sh[i];
        stat = r * (1.0f / HID);
    }
    __syncthreads();
    const float mu = stat;

    float s2 = 0.f;
#pragma unroll
    for (int i = 0; i < 4; i++) { float d = v[i] - mu; s2 += d * d; }
    s2 = warpSum(s2);
    __syncthreads();
    if (lane == 0) sh[wp] = s2;
    __syncthreads();
    if (threadIdx.x == 0) {
        float r = 0.f;
#pragma unroll
        for (int i = 0; i < 8; i++) r += sh[i];
        stat = rsqrtf(r * (1.0f / HID) + 1e-5f);
    }
    __syncthreads();
    const float rs = stat;

    __nv_bfloat16* orow = out + (size_t)t * HID;
#pragma unroll
    for (int i = 0; i < 4; i++) {
        int c = threadIdx.x + i * 256;
        orow[c] = __float2bfloat16((v[i] - mu) * rs * w[c] + b[c]);
    }
}

// ---------------- merged weight convert fp32 -> bf16 (4 arrays via grid.y) ----------
__global__ __launch_bounds__(256)
void cvt4_kernel(const float* __restrict__ s0, __nv_bfloat16* __restrict__ d0, int n0,
                 const float* __restrict__ s1, __nv_bfloat16* __restrict__ d1, int n1,
                 const float* __restrict__ s2, __nv_bfloat16* __restrict__ d2, int n2,
                 const float* __restrict__ s3, __nv_bfloat16* __restrict__ d3, int n3)
{
    const float* src; __nv_bfloat16* dst; int n;
    switch (blockIdx.y) {
        case 0: src = s0; dst = d0; n = n0; break;
        case 1: src = s1; dst = d1; n = n1; break;
        case 2: src = s2; dst = d2; n = n2; break;
        default: src = s3; dst = d3; n = n3; break;
    }
    int i = blockIdx.x * 256 + threadIdx.x;
    if (i < n) {
        float4 v = ((const float4*)src)[i];
        uint2 o;
        o.x = pack_bf2(v.x, v.y);
        o.y = pack_bf2(v.z, v.w);
        ((uint2*)dst)[i] = o;
    }
}

// ---------------- flash attention: ctx = softmax(QK^T/8 + alibi, causal) V ----------
// 128 threads, 64-row q-tile, 4 warps x 16 q-rows x full 128 k-tile.
// grid (32 qtiles [reversed], B*NH). 2 CTAs/SM (reg-limited), V via ldmatrix.trans.
__global__ __launch_bounds__(128)
void flash_kernel(const __nv_bfloat16* __restrict__ qkv,
                  const float* __restrict__ alibi,
                  __nv_bfloat16* __restrict__ ctx)
{
    extern __shared__ __nv_bfloat16 sm[];
    const int tid = threadIdx.x, wid = tid >> 5, lane = tid & 31;
    const int qt = (int)gridDim.x - 1 - (int)blockIdx.x;   // big tiles first
    const int z = blockIdx.y, b = z >> 4, h = z & 15;

    const uint32_t qsa = smem_u32(sm);                                  // Q: 64 x KPQ
    const uint32_t ksa[2] = { qsa + 64 * KPQ * 2, qsa + (64 + 128) * KPQ * 2 };
    const uint32_t vsa[2] = { qsa + (64 + 256) * KPQ * 2, qsa + (64 + 384) * KPQ * 2 };

    const __nv_bfloat16* Qg = qkv + ((size_t)(b * SEQ) + qt * 64) * QKVDIM + h * DHEAD;
    const __nv_bfloat16* Kg = qkv + (size_t)(b * SEQ) * QKVDIM + HID + h * DHEAD;
    const __nv_bfloat16* Vg = qkv + (size_t)(b * SEQ) * QKVDIM + 2 * HID + h * DHEAD;
    const float slope = alibi[(size_t)z * SEQ + 1];   // alibi[...,c] == slope*c exactly

    {
#pragma unroll
        for (int it = 0; it < 4; it++) {            // Q: 64 rows
            int idx = tid + it * 128, row = idx >> 3, u = idx & 7;
            cp16(qsa + (uint32_t)(row * KPQ + u * 8) * 2, Qg + (size_t)row * QKVDIM + u * 8);
        }
#pragma unroll
        for (int it = 0; it < 8; it++) {            // K: 128 rows
            int idx = tid + it * 128, row = idx >> 3, u = idx & 7;
            cp16(ksa[0] + (uint32_t)(row * KPQ + u * 8) * 2, Kg + (size_t)row * QKVDIM + u * 8);
        }
#pragma unroll
        for (int it = 0; it < 8; it++) {            // V: 128 rows
            int idx = tid + it * 128, row = idx >> 3, u = idx & 7;
            cp16(vsa[0] + (uint32_t)(row * KPQ + u * 8) * 2, Vg + (size_t)row * QKVDIM + u * 8);
        }
        CP_COMMIT;
    }
    CP_WAIT0;
    __syncthreads();

    uint32_t aQ[4][4];
#pragma unroll
    for (int kc = 0; kc < 4; kc++) {
        int row = wid * 16 + (lane & 7) + ((lane >> 3) & 1) * 8;
        int col = kc * 16 + ((lane >> 4) & 1) * 8;
        ldmx4(aQ[kc], qsa + (uint32_t)(row * KPQ + col) * 2);
    }

    float m0 = -1e30f, m1 = -1e30f, l0 = 0.f, l1 = 0.f;
    float oacc[8][4];
#pragma unroll
    for (int i = 0; i < 8; i++)
#pragma unroll
        for (int j = 0; j < 4; j++) oacc[i][j] = 0.f;

    const int rg0 = qt * 64 + wid * 16 + (lane >> 2);
    const int rg1 = rg0 + 8;
    const int KT = (qt >> 1) + 1;

    for (int kt = 0; kt < KT; kt++) {
        const int cur = kt & 1;
        if (kt + 1 < KT) {
            const __nv_bfloat16* Kn = Kg + (size_t)(kt + 1) * 128 * QKVDIM;
            const __nv_bfloat16* Vn = Vg + (size_t)(kt + 1) * 128 * QKVDIM;
#pragma unroll
            for (int it = 0; it < 8; it++) {
                int idx = tid + it * 128, row = idx >> 3, u = idx & 7;
                cp16(ksa[cur ^ 1] + (uint32_t)(row * KPQ + u * 8) * 2, Kn + (size_t)row * QKVDIM + u * 8);
            }
#pragma unroll
            for (int it = 0; it < 8; it++) {
                int idx = tid + it * 128, row = idx >> 3, u = idx & 7;
                cp16(vsa[cur ^ 1] + (uint32_t)(row * KPQ + u * 8) * 2, Vn + (size_t)row * QKVDIM + u * 8);
            }
            CP_COMMIT;
        }

        float sacc[16][4];
#pragma unroll
        for (int i = 0; i < 16; i++)
#pragma unroll
            for (int j = 0; j < 4; j++) sacc[i][j] = 0.f;
#pragma unroll
        for (int kc = 0; kc < 4; kc++) {
#pragma unroll
            for (int nb = 0; nb < 8; nb++) {
                uint32_t r[4];
                int row = nb * 16 + (lane & 7) + ((lane >> 4) & 1) * 8;
                int col = kc * 16 + ((lane >> 3) & 1) * 8;
                ldmx4(r, ksa[cur] + (uint32_t)(row * KPQ + col) * 2);
                mma16816(sacc[2 * nb], aQ[kc], r);
                mma16816(sacc[2 * nb + 1], aQ[kc], r + 2);
            }
        }

        // scale + alibi (+causal mask only on the diagonal tile) + row max
        float mx0 = -1e30f, mx1 = -1e30f;
        const int cb = kt * 128 + (lane & 3) * 2;
        if (kt == KT - 1) {
#pragma unroll
            for (int nt = 0; nt < 16; nt++) {
                int c0 = cb + nt * 8, c1 = c0 + 1;
                float a0 = slope * (float)c0, a1 = slope * (float)c1;
                float s0 = (c0 <= rg0) ? fmaf(sacc[nt][0], 0.125f, a0) : -1e30f;
                float s1 = (c1 <= rg0) ? fmaf(sacc[nt][1], 0.125f, a1) : -1e30f;
                float s2 = (c0 <= rg1) ? fmaf(sacc[nt][2], 0.125f, a0) : -1e30f;
                float s3 = (c1 <= rg1) ? fmaf(sacc[nt][3], 0.125f, a1) : -1e30f;
                sacc[nt][0] = s0; sacc[nt][1] = s1; sacc[nt][2] = s2; sacc[nt][3] = s3;
                mx0 = fmaxf(mx0, fmaxf(s0, s1)); mx1 = fmaxf(mx1, fmaxf(s2, s3));
            }
        } else {
#pragma unroll
            for (int nt = 0; nt < 16; nt++) {
                int c0 = cb + nt * 8, c1 = c0 + 1;
                float a0 = slope * (float)c0, a1 = slope * (float)c1;
                float s0 = fmaf(sacc[nt][0], 0.125f, a0);
                float s1 = fmaf(sacc[nt][1], 0.125f, a1);
                float s2 = fmaf(sacc[nt][2], 0.125f, a0);
                float s3 = fmaf(sacc[nt][3], 0.125f, a1);
                sacc[nt][0] = s0; sacc[nt][1] = s1; sacc[nt][2] = s2; sacc[nt][3] = s3;
                mx0 = fmaxf(mx0, fmaxf(s0, s1)); mx1 = fmaxf(mx1, fmaxf(s2, s3));
            }
        }
        mx0 = fmaxf(mx0, __shfl_xor_sync(0xffffffffu, mx0, 1));
        mx0 = fmaxf(mx0, __shfl_xor_sync(0xffffffffu, mx0, 2));
        mx1 = fmaxf(mx1, __shfl_xor_sync(0xffffffffu, mx1, 1));
        mx1 = fmaxf(mx1, __shfl_xor_sync(0xffffffffu, mx1, 2));

        const float mn0 = fmaxf(m0, mx0), mn1 = fmaxf(m1, mx1);
        const float sc0 = __expf(m0 - mn0), sc1 = __expf(m1 - mn1);
        float rs0 = 0.f, rs1 = 0.f;
#pragma unroll
        for (int nt = 0; nt < 16; nt++) {
            float p0 = __expf(sacc[nt][0] - mn0), p1 = __expf(sacc[nt][1] - mn0);
            float p2 = __expf(sacc[nt][2] - mn1), p3 = __expf(sacc[nt][3] - mn1);
            sacc[nt][0] = p0; sacc[nt][1] = p1; sacc[nt][2] = p2; sacc[nt][3] = p3;
            rs0 += p0 + p1; rs1 += p2 + p3;
        }
        rs0 += __shfl_xor_sync(0xffffffffu, rs0, 1);
        rs0 += __shfl_xor_sync(0xffffffffu, rs0, 2);
        rs1 += __shfl_xor_sync(0xffffffffu, rs1, 1);
        rs1 += __shfl_xor_sync(0xffffffffu, rs1, 2);
        l0 = l0 * sc0 + rs0; l1 = l1 * sc1 + rs1;
        m0 = mn0; m1 = mn1;
#pragma unroll
        for (int nt = 0; nt < 8; nt++) {
            oacc[nt][0] *= sc0; oacc[nt][1] *= sc0;
            oacc[nt][2] *= sc1; oacc[nt][3] *= sc1;
        }

        // O += P V : B fragments trans-loaded from row-major V [kv, d]
#pragma unroll
        for (int kc2 = 0; kc2 < 8; kc2++) {
            uint32_t pa[4] = {
                pack_bf2(sacc[2 * kc2][0],     sacc[2 * kc2][1]),
                pack_bf2(sacc[2 * kc2][2],     sacc[2 * kc2][3]),
                pack_bf2(sacc[2 * kc2 + 1][0], sacc[2 * kc2 + 1][1]),
                pack_bf2(sacc[2 * kc2 + 1][2], sacc[2 * kc2 + 1][3]) };
#pragma unroll
            for (int nb = 0; nb < 4; nb++) {
                uint32_t r[4];
                int row = kc2 * 16 + (lane & 7) + ((lane >> 3) & 1) * 8;   // kv
                int col = nb * 16 + ((lane >> 4) & 1) * 8;                  // d
                ldmx4t(r, vsa[cur] + (uint32_t)(row * KPQ + col) * 2);
                mma16816(oacc[2 * nb], pa, r);
                mma16816(oacc[2 * nb + 1], pa, r + 2);
            }
        }

        if (kt + 1 < KT) CP_WAIT0;
        __syncthreads();
    }

    const float inv0 = 1.0f / l0, inv1 = 1.0f / l1;
    const int tok0 = b * SEQ + qt * 64 + wid * 16 + (lane >> 2);
#pragma unroll
    for (int nt = 0; nt < 8; nt++) {
        int c = h * DHEAD + nt * 8 + (lane & 3) * 2;
        *(uint32_t*)(ctx + (size_t)tok0 * HID + c) = pack_bf2(oacc[nt][0] * inv0, oacc[nt][1] * inv0);
        *(uint32_t*)(ctx + (size_t)(tok0 + 8) * HID + c) = pack_bf2(oacc[nt][2] * inv1, oacc[nt][3] * inv1);
    }
}

// ---------------- bf16 NT GEMM: 256 threads, warp tile 32x64, K-chunk 32, 3-stage ----
// EPI: 0 = bias -> bf16, 1 = bias+gelu -> bf16, 2 = bias+residual -> fp32
#define STG_B (128 * KPAD * 2)   // bytes per stage per operand (10240)

template<int EPI>
__global__ __launch_bounds__(256, 2)
void mm_gemm(const __nv_bfloat16* __restrict__ A, int lda,
             const __nv_bfloat16* __restrict__ B, int ldb,
             const float* __restrict__ bias, const float* __restrict__ res,
             void* __restrict__ Cout, int ldc, int K)
{
    extern __shared__ __nv_bfloat16 smbuf[];
    const uint32_t as0 = smem_u32(smbuf);
    const uint32_t bs0 = as0 + 3 * STG_B;
    const int tid = threadIdx.x, wid = tid >> 5, lane = tid & 31;
    const int wm = wid & 3, wn = wid >> 2;
    const int rowB = blockIdx.y * 128, colB = blockIdx.x * 128;
    const __nv_bfloat16* Ag = A + (size_t)rowB * lda;
    const __nv_bfloat16* Bg = B + (size_t)colB * ldb;

    float acc[2][8][4];
#pragma unroll
    for (int i = 0; i < 2; i++)
#pragma unroll
        for (int j = 0; j < 8; j++)
#pragma unroll
            for (int k = 0; k < 4; k++) acc[i][j][k] = 0.f;

    const int NCH = K >> 5;
    cp_chunk(as0, Ag, lda, tid); cp_chunk(bs0, Bg, ldb, tid); CP_COMMIT;
    cp_chunk(as0 + STG_B, Ag + 32, lda, tid); cp_chunk(bs0 + STG_B, Bg + 32, ldb, tid); CP_COMMIT;

    for (int kc = 0; kc < NCH; kc++) {
        if (kc == NCH - 1) { CP_WAIT0; } else { CP_WAIT1; }
        __syncthreads();
        if (kc + 2 < NCH) {
            int st = (kc + 2) % 3;
            cp_chunk(as0 + st * STG_B, Ag + (kc + 2) * 32, lda, tid);
            cp_chunk(bs0 + st * STG_B, Bg + (kc + 2) * 32, ldb, tid);
            CP_COMMIT;
        }
        int st = kc % 3;
        mma_chunk(acc, as0 + st * STG_B, bs0 + st * STG_B, wm, wn, lane);
    }

#pragma unroll
    for (int mt = 0; mt < 2; mt++) {
#pragma unroll
        for (int nt = 0; nt < 8; nt++) {
            const float* ac = acc[mt][nt];
            const int r0 = rowB + wm * 32 + mt * 16 + (lane >> 2);
            const int c = colB + wn * 64 + nt * 8 + (lane & 3) * 2;
            const float b0 = bias[c], b1 = bias[c + 1];
            if (EPI == 2) {
                float* C = (float*)Cout;
                float2 ra = *(const float2*)(res + (size_t)r0 * ldc + c);
                float2 rb = *(const float2*)(res + (size_t)(r0 + 8) * ldc + c);
                float2 o0 = { ac[0] + b0 + ra.x, ac[1] + b1 + ra.y };
                float2 o1 = { ac[2] + b0 + rb.x, ac[3] + b1 + rb.y };
                *(float2*)(C + (size_t)r0 * ldc + c) = o0;
                *(float2*)(C + (size_t)(r0 + 8) * ldc + c) = o1;
            } else {
                __nv_bfloat16* C = (__nv_bfloat16*)Cout;
                float v0 = ac[0] + b0, v1 = ac[1] + b1;
                float v2 = ac[2] + b0, v3 = ac[3] + b1;
                if (EPI == 1) { v0 = gelu_f(v0); v1 = gelu_f(v1); v2 = gelu_f(v2); v3 = gelu_f(v3); }
                *(uint32_t*)(C + (size_t)r0 * ldc + c) = pack_bf2(v0, v1);
                *(uint32_t*)(C + (size_t)(r0 + 8) * ldc + c) = pack_bf2(v2, v3);
            }
        }
    }
}

// ---------------- launch ----------------
extern "C" void kernel_launch(void* const* d_in, const int* in_sizes, int n_in,
                              void* d_out, int out_size)
{
    (void)in_sizes; (void)n_in; (void)out_size;
    const float* hidden  = (const float*)d_in[0];
    const float* alibi   = (const float*)d_in[1];
    const float* qkv_w   = (const float*)d_in[2];
    const float* qkv_b   = (const float*)d_in[3];
    const float* dense_w = (const float*)d_in[4];
    const float* dense_b = (const float*)d_in[5];
    const float* w1      = (const float*)d_in[6];
    const float* b1      = (const float*)d_in[7];
    const float* w2      = (const float*)d_in[8];
    const float* b2      = (const float*)d_in[9];
    const float* ln1w    = (const float*)d_in[10];
    const float* ln1b    = (const float*)d_in[11];
    const float* ln2w    = (const float*)d_in[12];
    const float* ln2b    = (const float*)d_in[13];
    float* x = (float*)d_out;

    __nv_bfloat16 *ph, *pqkv, *pctx, *pff, *pwq, *pwd, *pw1, *pw2;
    cudaGetSymbolAddress((void**)&ph,   g_h);
    cudaGetSymbolAddress((void**)&pqkv, g_qkv);
    cudaGetSymbolAddress((void**)&pctx, g_ctx);
    cudaGetSymbolAddress((void**)&pff,  g_ff);
    cudaGetSymbolAddress((void**)&pwq,  g_wq);
    cudaGetSymbolAddress((void**)&pwd,  g_wd);
    cudaGetSymbolAddress((void**)&pw1,  g_w1);
    cudaGetSymbolAddress((void**)&pw2,  g_w2);

    const int GEMM_SMEM  = 6 * STG_B;                          // 61440
    const int FLASH_SMEM = (64 + 4 * 128) * KPQ * 2;           // 82944
    cudaFuncSetAttribute(mm_gemm<0>, cudaFuncAttributeMaxDynamicSharedMemorySize, GEMM_SMEM);
    cudaFuncSetAttribute(mm_gemm<1>, cudaFuncAttributeMaxDynamicSharedMemorySize, GEMM_SMEM);
    cudaFuncSetAttribute(mm_gemm<2>, cudaFuncAttributeMaxDynamicSharedMemorySize, GEMM_SMEM);
    cudaFuncSetAttribute(flash_kernel, cudaFuncAttributeMaxDynamicSharedMemorySize, FLASH_SMEM);

    cudaMemcpyAsync(x, hidden, sizeof(float) * (size_t)NTOK * HID, cudaMemcpyDeviceToDevice);

    // weights -> bf16 (all 4 arrays in one launch)
    const int nq = NLAYER * QKVDIM * HID / 4, nd = NLAYER * HID * HID / 4;
    const int n1 = NLAYER * FFDIM * HID / 4, n2 = NLAYER * HID * FFDIM / 4;
    int nmax = n1 > nq ? n1 : nq;
    cvt4_kernel<<<dim3((nmax + 255) / 256, 4), 256>>>(
        qkv_w, pwq, nq, dense_w, pwd, nd, w1, pw1, n1, w2, pw2, n2);

    for (int l = 0; l < NLAYER; l++) {
        // --- attention ---
        ln_kernel<<<NTOK, 256>>>(x, ln1w + l * HID, ln1b + l * HID, ph);
        mm_gemm<0><<<dim3(QKVDIM / 128, NTOK / 128), 256, GEMM_SMEM>>>(
            ph, HID, pwq + (size_t)l * QKVDIM * HID, HID,
            qkv_b + (size_t)l * QKVDIM, nullptr, pqkv, QKVDIM, HID);
        flash_kernel<<<dim3(SEQ / 64, BATCH * NHEAD), 128, FLASH_SMEM>>>(pqkv, alibi, pctx);
        mm_gemm<2><<<dim3(HID / 128, NTOK / 128), 256, GEMM_SMEM>>>(
            pctx, HID, pwd + (size_t)l * HID * HID, HID,
            dense_b + (size_t)l * HID, x, x, HID, HID);
        // --- MLP ---
        ln_kernel<<<NTOK, 256>>>(x, ln2w + l * HID, ln2b + l * HID, ph);
        mm_gemm<1><<<dim3(FFDIM / 128, NTOK / 128), 256, GEMM_SMEM>>>(
            ph, HID, pw1 + (size_t)l * FFDIM * HID, HID,
            b1 + (size_t)l * FFDIM, nullptr, pff, FFDIM, HID);
        mm_gemm<2><<<dim3(HID / 128, NTOK / 128), 256, GEMM_SMEM>>>(
            pff, FFDIM, pw2 + (size_t)l * HID * FFDIM, FFDIM,
            b2 + (size_t)l * HID, x, x, HID, FFDIM);
    }
}

// round 15
// speedup vs baseline: 1.3973x; 1.0094x over previous
#include <cuda_runtime.h>
#include <cuda_bf16.h>
#include <math.h>
#include <stdint.h>

#define NLAYER 2
#define BATCH  2
#define SEQ    2048
#define HID    1024
#define NHEAD  16
#define DHEAD  64
#define FFDIM  4096
#define NTOK   (BATCH*SEQ)      // 4096
#define QKVDIM (3*HID)          // 3072
#define KPAD   40               // GEMM: 32-elem K chunk padded to 40
#define KPQ    72               // flash: 64-elem rows padded to 72

// ---------------- scratch (device globals) ----------------
__device__ __nv_bfloat16 g_h[NTOK*HID];
__device__ __nv_bfloat16 g_qkv[(size_t)NTOK*QKVDIM];
__device__ __nv_bfloat16 g_ctx[NTOK*HID];
__device__ __nv_bfloat16 g_ff[(size_t)NTOK*FFDIM];
__device__ __nv_bfloat16 g_wq[(size_t)NLAYER*QKVDIM*HID];
__device__ __nv_bfloat16 g_wd[(size_t)NLAYER*HID*HID];
__device__ __nv_bfloat16 g_w1[(size_t)NLAYER*FFDIM*HID];
__device__ __nv_bfloat16 g_w2[(size_t)NLAYER*HID*FFDIM];

// ---------------- helpers ----------------
__device__ __forceinline__ uint32_t smem_u32(const void* p) {
    uint32_t a;
    asm("{ .reg .u64 t; cvta.to.shared.u64 t, %1; cvt.u32.u64 %0, t; }" : "=r"(a) : "l"(p));
    return a;
}
__device__ __forceinline__ void cp16(uint32_t s, const void* g) {
    asm volatile("cp.async.cg.shared.global [%0], [%1], 16;" :: "r"(s), "l"(g));
}
#define CP_COMMIT asm volatile("cp.async.commit_group;")
#define CP_WAIT1  asm volatile("cp.async.wait_group 1;")
#define CP_WAIT0  asm volatile("cp.async.wait_group 0;")

__device__ __forceinline__ void ldmx4(uint32_t* r, uint32_t addr) {
    asm volatile("ldmatrix.sync.aligned.m8n8.x4.shared.b16 {%0,%1,%2,%3}, [%4];"
                 : "=r"(r[0]), "=r"(r[1]), "=r"(r[2]), "=r"(r[3]) : "r"(addr));
}
__device__ __forceinline__ void ldmx4t(uint32_t* r, uint32_t addr) {
    asm volatile("ldmatrix.sync.aligned.m8n8.x4.trans.shared.b16 {%0,%1,%2,%3}, [%4];"
                 : "=r"(r[0]), "=r"(r[1]), "=r"(r[2]), "=r"(r[3]) : "r"(addr));
}
__device__ __forceinline__ void mma16816(float* c, const uint32_t* a, const uint32_t* b) {
    asm volatile("mma.sync.aligned.m16n8k16.row.col.f32.bf16.bf16.f32 "
                 "{%0,%1,%2,%3}, {%4,%5,%6,%7}, {%8,%9}, {%0,%1,%2,%3};"
                 : "+f"(c[0]), "+f"(c[1]), "+f"(c[2]), "+f"(c[3])
                 : "r"(a[0]), "r"(a[1]), "r"(a[2]), "r"(a[3]), "r"(b[0]), "r"(b[1]));
}
__device__ __forceinline__ uint32_t pack_bf2(float a, float b) {
    __nv_bfloat162 h = __floats2bfloat162_rn(a, b);
    return *(uint32_t*)&h;
}
__device__ __forceinline__ float gelu_f(float v) {
    return 0.5f * v * (1.0f + erff(v * 0.70710678118654752440f));
}
__device__ __forceinline__ float warpSum(float v) {
#pragma unroll
    for (int o = 16; o > 0; o >>= 1) v += __shfl_xor_sync(0xffffffffu, v, o);
    return v;
}

// load 128 x 32 bf16 chunk from g (row stride ld elems) into smem (KPAD-elem rows)
__device__ __forceinline__ void cp_chunk(uint32_t sbase, const __nv_bfloat16* g, int ld, int tid) {
#pragma unroll
    for (int it = 0; it < 2; it++) {
        int idx = tid + it * 256;
        int row = idx >> 2, q = idx & 3;
        cp16(sbase + (uint32_t)(row * KPAD + q * 8) * 2, g + (size_t)row * ld + q * 8);
    }
}

// one 32-wide K-chunk of warp-level MMAs (128x128 CTA tile, 4x2 warps, 32x64 warp tile)
__device__ __forceinline__ void mma_chunk(float (&acc)[2][8][4], uint32_t abase, uint32_t bbase,
                                          int wm, int wn, int lane) {
#pragma unroll
    for (int ks = 0; ks < 32; ks += 16) {
        uint32_t a[2][4];
#pragma unroll
        for (int mt = 0; mt < 2; mt++) {
            int row = wm * 32 + mt * 16 + (lane & 7) + ((lane >> 3) & 1) * 8;
            int col = ks + ((lane >> 4) & 1) * 8;
            ldmx4(a[mt], abase + (uint32_t)(row * KPAD + col) * 2);
        }
        uint32_t bf[8][2];
#pragma unroll
        for (int nb = 0; nb < 4; nb++) {
            int row = wn * 64 + nb * 16 + (lane & 7) + ((lane >> 4) & 1) * 8;
            int col = ks + ((lane >> 3) & 1) * 8;
            uint32_t r[4];
            ldmx4(r, bbase + (uint32_t)(row * KPAD + col) * 2);
            bf[2 * nb][0] = r[0]; bf[2 * nb][1] = r[1];
            bf[2 * nb + 1][0] = r[2]; bf[2 * nb + 1][1] = r[3];
        }
#pragma unroll
        for (int mt = 0; mt < 2; mt++)
#pragma unroll
            for (int nt = 0; nt < 8; nt++)
                mma16816(acc[mt][nt], a[mt], bf[nt]);
    }
}

// ---------------- LayerNorm (fp32 in, bf16 out) ----------------
__global__ __launch_bounds__(256)
void ln_kernel(const float* __restrict__ x, const float* __restrict__ w,
               const float* __restrict__ b, __nv_bfloat16* __restrict__ out)
{
    __shared__ float sh[8];
    __shared__ float stat;
    const int t = blockIdx.x;
    const float* xr = x + (size_t)t * HID;
    const int lane = threadIdx.x & 31, wp = threadIdx.x >> 5;

    float v[4];
    float s = 0.f;
#pragma unroll
    for (int i = 0; i < 4; i++) { v[i] = xr[threadIdx.x + i * 256]; s += v[i]; }
    s = warpSum(s);
    if (lane == 0) sh[wp] = s;
    __syncthreads();
    if (threadIdx.x == 0) {
        float r = 0.f;
#pragma unroll
        for (int i = 0; i < 8; i++) r += sh[i];
        stat = r * (1.0f / HID);
    }
    __syncthreads();
    const float mu = stat;

    float s2 = 0.f;
#pragma unroll
    for (int i = 0; i < 4; i++) { float d = v[i] - mu; s2 += d * d; }
    s2 = warpSum(s2);
    __syncthreads();
    if (lane == 0) sh[wp] = s2;
    __syncthreads();
    if (threadIdx.x == 0) {
        float r = 0.f;
#pragma unroll
        for (int i = 0; i < 8; i++) r += sh[i];
        stat = rsqrtf(r * (1.0f / HID) + 1e-5f);
    }
    __syncthreads();
    const float rs = stat;

    __nv_bfloat16* orow = out + (size_t)t * HID;
#pragma unroll
    for (int i = 0; i < 4; i++) {
        int c = threadIdx.x + i * 256;
        orow[c] = __float2bfloat16((v[i] - mu) * rs * w[c] + b[c]);
    }
}

// ---------------- merged weight convert fp32 -> bf16 (4 arrays via grid.y) ----------
__global__ __launch_bounds__(256)
void cvt4_kernel(const float* __restrict__ s0, __nv_bfloat16* __restrict__ d0, int n0,
                 const float* __restrict__ s1, __nv_bfloat16* __restrict__ d1, int n1,
                 const float* __restrict__ s2, __nv_bfloat16* __restrict__ d2, int n2,
                 const float* __restrict__ s3, __nv_bfloat16* __restrict__ d3, int n3)
{
    const float* src; __nv_bfloat16* dst; int n;
    switch (blockIdx.y) {
        case 0: src = s0; dst = d0; n = n0; break;
        case 1: src = s1; dst = d1; n = n1; break;
        case 2: src = s2; dst = d2; n = n2; break;
        default: src = s3; dst = d3; n = n3; break;
    }
    int i = blockIdx.x * 256 + threadIdx.x;
    if (i < n) {
        float4 v = ((const float4*)src)[i];
        uint2 o;
        o.x = pack_bf2(v.x, v.y);
        o.y = pack_bf2(v.z, v.w);
        ((uint2*)dst)[i] = o;
    }
}

// ---------------- flash attention: ctx = softmax(QK^T/8 + alibi, causal) V ----------
// 128 threads, 64-row q-tile, 4 warps x 16 q-rows x full 128 k-tile.
// Static softmax shift m = slope*row (softmax is shift-invariant; QK/8 is O(1) so no
// overflow). No running max, no oacc rescale. Q smem overlays V buffer 1 (freed to
// registers before first V[1] prefetch) -> 73728 B smem, 3 CTAs/SM.
__global__ __launch_bounds__(128, 3)
void flash_kernel(const __nv_bfloat16* __restrict__ qkv,
                  const float* __restrict__ alibi,
                  __nv_bfloat16* __restrict__ ctx)
{
    extern __shared__ __nv_bfloat16 sm[];
    const int tid = threadIdx.x, wid = tid >> 5, lane = tid & 31;
    const int qt = (int)gridDim.x - 1 - (int)blockIdx.x;   // big tiles first
    const int z = blockIdx.y, b = z >> 4, h = z & 15;

    const uint32_t base = smem_u32(sm);
    const uint32_t TILE = 128 * KPQ * 2;                    // 18432
    const uint32_t ksa[2] = { base, base + TILE };
    const uint32_t vsa[2] = { base + 2 * TILE, base + 3 * TILE };
    const uint32_t qsa = vsa[1];                            // Q overlays V buffer 1

    const __nv_bfloat16* Qg = qkv + ((size_t)(b * SEQ) + qt * 64) * QKVDIM + h * DHEAD;
    const __nv_bfloat16* Kg = qkv + (size_t)(b * SEQ) * QKVDIM + HID + h * DHEAD;
    const __nv_bfloat16* Vg = qkv + (size_t)(b * SEQ) * QKVDIM + 2 * HID + h * DHEAD;
    const float slope = alibi[(size_t)z * SEQ + 1];   // alibi[...,c] == slope*c exactly

    {
#pragma unroll
        for (int it = 0; it < 4; it++) {            // Q: 64 rows (into vsa[1] slot)
            int idx = tid + it * 128, row = idx >> 3, u = idx & 7;
            cp16(qsa + (uint32_t)(row * KPQ + u * 8) * 2, Qg + (size_t)row * QKVDIM + u * 8);
        }
#pragma unroll
        for (int it = 0; it < 8; it++) {            // K: 128 rows
            int idx = tid + it * 128, row = idx >> 3, u = idx & 7;
            cp16(ksa[0] + (uint32_t)(row * KPQ + u * 8) * 2, Kg + (size_t)row * QKVDIM + u * 8);
        }
#pragma unroll
        for (int it = 0; it < 8; it++) {            // V: 128 rows
            int idx = tid + it * 128, row = idx >> 3, u = idx & 7;
            cp16(vsa[0] + (uint32_t)(row * KPQ + u * 8) * 2, Vg + (size_t)row * QKVDIM + u * 8);
        }
        CP_COMMIT;
    }
    CP_WAIT0;
    __syncthreads();

    uint32_t aQ[4][4];
#pragma unroll
    for (int kc = 0; kc < 4; kc++) {
        int row = wid * 16 + (lane & 7) + ((lane >> 3) & 1) * 8;
        int col = kc * 16 + ((lane >> 4) & 1) * 8;
        ldmx4(aQ[kc], qsa + (uint32_t)(row * KPQ + col) * 2);
    }
    __syncthreads();   // all aQ consumed before V[1] prefetch overwrites the Q region

    const int rg0 = qt * 64 + wid * 16 + (lane >> 2);
    const int rg1 = rg0 + 8;
    const float m0 = slope * (float)rg0;       // static softmax shift per row
    const float m1 = slope * (float)rg1;

    float l0 = 0.f, l1 = 0.f;
    float oacc[8][4];
#pragma unroll
    for (int i = 0; i < 8; i++)
#pragma unroll
        for (int j = 0; j < 4; j++) oacc[i][j] = 0.f;

    const int KT = (qt >> 1) + 1;

    for (int kt = 0; kt < KT; kt++) {
        const int cur = kt & 1;
        if (kt + 1 < KT) {
            const __nv_bfloat16* Kn = Kg + (size_t)(kt + 1) * 128 * QKVDIM;
            const __nv_bfloat16* Vn = Vg + (size_t)(kt + 1) * 128 * QKVDIM;
#pragma unroll
            for (int it = 0; it < 8; it++) {
                int idx = tid + it * 128, row = idx >> 3, u = idx & 7;
                cp16(ksa[cur ^ 1] + (uint32_t)(row * KPQ + u * 8) * 2, Kn + (size_t)row * QKVDIM + u * 8);
            }
#pragma unroll
            for (int it = 0; it < 8; it++) {
                int idx = tid + it * 128, row = idx >> 3, u = idx & 7;
                cp16(vsa[cur ^ 1] + (uint32_t)(row * KPQ + u * 8) * 2, Vn + (size_t)row * QKVDIM + u * 8);
            }
            CP_COMMIT;
        }

        float sacc[16][4];
#pragma unroll
        for (int i = 0; i < 16; i++)
#pragma unroll
            for (int j = 0; j < 4; j++) sacc[i][j] = 0.f;
#pragma unroll
        for (int kc = 0; kc < 4; kc++) {
#pragma unroll
            for (int nb = 0; nb < 8; nb++) {
                uint32_t r[4];
                int row = nb * 16 + (lane & 7) + ((lane >> 4) & 1) * 8;
                int col = kc * 16 + ((lane >> 3) & 1) * 8;
                ldmx4(r, ksa[cur] + (uint32_t)(row * KPQ + col) * 2);
                mma16816(sacc[2 * nb], aQ[kc], r);
                mma16816(sacc[2 * nb + 1], aQ[kc], r + 2);
            }
        }

        // p = exp(QK/8 + slope*(c) - m), mask only on the diagonal tile
        float rs0 = 0.f, rs1 = 0.f;
        const int cb = kt * 128 + (lane & 3) * 2;
        if (kt == KT - 1) {
#pragma unroll
            for (int nt = 0; nt < 16; nt++) {
                int c0 = cb + nt * 8, c1 = c0 + 1;
                float a0 = slope * (float)c0, a1 = slope * (float)c1;
                float p0 = (c0 <= rg0) ? __expf(fmaf(sacc[nt][0], 0.125f, a0) - m0) : 0.f;
                float p1 = (c1 <= rg0) ? __expf(fmaf(sacc[nt][1], 0.125f, a1) - m0) : 0.f;
                float p2 = (c0 <= rg1) ? __expf(fmaf(sacc[nt][2], 0.125f, a0) - m1) : 0.f;
                float p3 = (c1 <= rg1) ? __expf(fmaf(sacc[nt][3], 0.125f, a1) - m1) : 0.f;
                sacc[nt][0] = p0; sacc[nt][1] = p1; sacc[nt][2] = p2; sacc[nt][3] = p3;
                rs0 += p0 + p1; rs1 += p2 + p3;
            }
        } else {
#pragma unroll
            for (int nt = 0; nt < 16; nt++) {
                int c0 = cb + nt * 8, c1 = c0 + 1;
                float a0 = slope * (float)c0, a1 = slope * (float)c1;
                float p0 = __expf(fmaf(sacc[nt][0], 0.125f, a0) - m0);
                float p1 = __expf(fmaf(sacc[nt][1], 0.125f, a1) - m0);
                float p2 = __expf(fmaf(sacc[nt][2], 0.125f, a0) - m1);
                float p3 = __expf(fmaf(sacc[nt][3], 0.125f, a1) - m1);
                sacc[nt][0] = p0; sacc[nt][1] = p1; sacc[nt][2] = p2; sacc[nt][3] = p3;
                rs0 += p0 + p1; rs1 += p2 + p3;
            }
        }
        rs0 += __shfl_xor_sync(0xffffffffu, rs0, 1);
        rs0 += __shfl_xor_sync(0xffffffffu, rs0, 2);
        rs1 += __shfl_xor_sync(0xffffffffu, rs1, 1);
        rs1 += __shfl_xor_sync(0xffffffffu, rs1, 2);
        l0 += rs0; l1 += rs1;

        // O += P V : B fragments trans-loaded from row-major V [kv, d]
#pragma unroll
        for (int kc2 = 0; kc2 < 8; kc2++) {
            uint32_t pa[4] = {
                pack_bf2(sacc[2 * kc2][0],     sacc[2 * kc2][1]),
                pack_bf2(sacc[2 * kc2][2],     sacc[2 * kc2][3]),
                pack_bf2(sacc[2 * kc2 + 1][0], sacc[2 * kc2 + 1][1]),
                pack_bf2(sacc[2 * kc2 + 1][2], sacc[2 * kc2 + 1][3]) };
#pragma unroll
            for (int nb = 0; nb < 4; nb++) {
                uint32_t r[4];
                int row = kc2 * 16 + (lane & 7) + ((lane >> 3) & 1) * 8;   // kv
                int col = nb * 16 + ((lane >> 4) & 1) * 8;                  // d
                ldmx4t(r, vsa[cur] + (uint32_t)(row * KPQ + col) * 2);
                mma16816(oacc[2 * nb], pa, r);
                mma16816(oacc[2 * nb + 1], pa, r + 2);
            }
        }

        if (kt + 1 < KT) CP_WAIT0;
        __syncthreads();
    }

    const float inv0 = 1.0f / l0, inv1 = 1.0f / l1;
    const int tok0 = b * SEQ + qt * 64 + wid * 16 + (lane >> 2);
#pragma unroll
    for (int nt = 0; nt < 8; nt++) {
        int c = h * DHEAD + nt * 8 + (lane & 3) * 2;
        *(uint32_t*)(ctx + (size_t)tok0 * HID + c) = pack_bf2(oacc[nt][0] * inv0, oacc[nt][1] * inv0);
        *(uint32_t*)(ctx + (size_t)(tok0 + 8) * HID + c) = pack_bf2(oacc[nt][2] * inv1, oacc[nt][3] * inv1);
    }
}

// ---------------- bf16 NT GEMM: 256 threads, warp tile 32x64, K-chunk 32, 3-stage ----
// EPI: 0 = bias -> bf16, 1 = bias+gelu -> bf16, 2 = bias+residual -> fp32
#define STG_B (128 * KPAD * 2)   // bytes per stage per operand (10240)

template<int EPI>
__global__ __launch_bounds__(256, 2)
void mm_gemm(const __nv_bfloat16* __restrict__ A, int lda,
             const __nv_bfloat16* __restrict__ B, int ldb,
             const float* __restrict__ bias, const float* __restrict__ res,
             void* __restrict__ Cout, int ldc, int K)
{
    extern __shared__ __nv_bfloat16 smbuf[];
    const uint32_t as0 = smem_u32(smbuf);
    const uint32_t bs0 = as0 + 3 * STG_B;
    const int tid = threadIdx.x, wid = tid >> 5, lane = tid & 31;
    const int wm = wid & 3, wn = wid >> 2;
    const int rowB = blockIdx.y * 128, colB = blockIdx.x * 128;
    const __nv_bfloat16* Ag = A + (size_t)rowB * lda;
    const __nv_bfloat16* Bg = B + (size_t)colB * ldb;

    float acc[2][8][4];
#pragma unroll
    for (int i = 0; i < 2; i++)
#pragma unroll
        for (int j = 0; j < 8; j++)
#pragma unroll
            for (int k = 0; k < 4; k++) acc[i][j][k] = 0.f;

    const int NCH = K >> 5;
    cp_chunk(as0, Ag, lda, tid); cp_chunk(bs0, Bg, ldb, tid); CP_COMMIT;
    cp_chunk(as0 + STG_B, Ag + 32, lda, tid); cp_chunk(bs0 + STG_B, Bg + 32, ldb, tid); CP_COMMIT;

    for (int kc = 0; kc < NCH; kc++) {
        if (kc == NCH - 1) { CP_WAIT0; } else { CP_WAIT1; }
        __syncthreads();
        if (kc + 2 < NCH) {
            int st = (kc + 2) % 3;
            cp_chunk(as0 + st * STG_B, Ag + (kc + 2) * 32, lda, tid);
            cp_chunk(bs0 + st * STG_B, Bg + (kc + 2) * 32, ldb, tid);
            CP_COMMIT;
        }
        int st = kc % 3;
        mma_chunk(acc, as0 + st * STG_B, bs0 + st * STG_B, wm, wn, lane);
    }

#pragma unroll
    for (int mt = 0; mt < 2; mt++) {
#pragma unroll
        for (int nt = 0; nt < 8; nt++) {
            const float* ac = acc[mt][nt];
            const int r0 = rowB + wm * 32 + mt * 16 + (lane >> 2);
            const int c = colB + wn * 64 + nt * 8 + (lane & 3) * 2;
            const float b0 = bias[c], b1 = bias[c + 1];
            if (EPI == 2) {
                float* C = (float*)Cout;
                float2 ra = *(const float2*)(res + (size_t)r0 * ldc + c);
                float2 rb = *(const float2*)(res + (size_t)(r0 + 8) * ldc + c);
                float2 o0 = { ac[0] + b0 + ra.x, ac[1] + b1 + ra.y };
                float2 o1 = { ac[2] + b0 + rb.x, ac[3] + b1 + rb.y };
                *(float2*)(C + (size_t)r0 * ldc + c) = o0;
                *(float2*)(C + (size_t)(r0 + 8) * ldc + c) = o1;
            } else {
                __nv_bfloat16* C = (__nv_bfloat16*)Cout;
                float v0 = ac[0] + b0, v1 = ac[1] + b1;
                float v2 = ac[2] + b0, v3 = ac[3] + b1;
                if (EPI == 1) { v0 = gelu_f(v0); v1 = gelu_f(v1); v2 = gelu_f(v2); v3 = gelu_f(v3); }
                *(uint32_t*)(C + (size_t)r0 * ldc + c) = pack_bf2(v0, v1);
                *(uint32_t*)(C + (size_t)(r0 + 8) * ldc + c) = pack_bf2(v2, v3);
            }
        }
    }
}

// ---------------- launch ----------------
extern "C" void kernel_launch(void* const* d_in, const int* in_sizes, int n_in,
                              void* d_out, int out_size)
{
    (void)in_sizes; (void)n_in; (void)out_size;
    const float* hidden  = (const float*)d_in[0];
    const float* alibi   = (const float*)d_in[1];
    const float* qkv_w   = (const float*)d_in[2];
    const float* qkv_b   = (const float*)d_in[3];
    const float* dense_w = (const float*)d_in[4];
    const float* dense_b = (const float*)d_in[5];
    const float* w1      = (const float*)d_in[6];
    const float* b1      = (const float*)d_in[7];
    const float* w2      = (const float*)d_in[8];
    const float* b2      = (const float*)d_in[9];
    const float* ln1w    = (const float*)d_in[10];
    const float* ln1b    = (const float*)d_in[11];
    const float* ln2w    = (const float*)d_in[12];
    const float* ln2b    = (const float*)d_in[13];
    float* x = (float*)d_out;

    __nv_bfloat16 *ph, *pqkv, *pctx, *pff, *pwq, *pwd, *pw1, *pw2;
    cudaGetSymbolAddress((void**)&ph,   g_h);
    cudaGetSymbolAddress((void**)&pqkv, g_qkv);
    cudaGetSymbolAddress((void**)&pctx, g_ctx);
    cudaGetSymbolAddress((void**)&pff,  g_ff);
    cudaGetSymbolAddress((void**)&pwq,  g_wq);
    cudaGetSymbolAddress((void**)&pwd,  g_wd);
    cudaGetSymbolAddress((void**)&pw1,  g_w1);
    cudaGetSymbolAddress((void**)&pw2,  g_w2);

    const int GEMM_SMEM  = 6 * STG_B;                // 61440
    const int FLASH_SMEM = 4 * 128 * KPQ * 2;        // 73728
    cudaFuncSetAttribute(mm_gemm<0>, cudaFuncAttributeMaxDynamicSharedMemorySize, GEMM_SMEM);
    cudaFuncSetAttribute(mm_gemm<1>, cudaFuncAttributeMaxDynamicSharedMemorySize, GEMM_SMEM);
    cudaFuncSetAttribute(mm_gemm<2>, cudaFuncAttributeMaxDynamicSharedMemorySize, GEMM_SMEM);
    cudaFuncSetAttribute(flash_kernel, cudaFuncAttributeMaxDynamicSharedMemorySize, FLASH_SMEM);

    cudaMemcpyAsync(x, hidden, sizeof(float) * (size_t)NTOK * HID, cudaMemcpyDeviceToDevice);

    // weights -> bf16 (all 4 arrays in one launch)
    const int nq = NLAYER * QKVDIM * HID / 4, nd = NLAYER * HID * HID / 4;
    const int n1 = NLAYER * FFDIM * HID / 4, n2 = NLAYER * HID * FFDIM / 4;
    int nmax = n1 > nq ? n1 : nq;
    cvt4_kernel<<<dim3((nmax + 255) / 256, 4), 256>>>(
        qkv_w, pwq, nq, dense_w, pwd, nd, w1, pw1, n1, w2, pw2, n2);

    for (int l = 0; l < NLAYER; l++) {
        // --- attention ---
        ln_kernel<<<NTOK, 256>>>(x, ln1w + l * HID, ln1b + l * HID, ph);
        mm_gemm<0><<<dim3(QKVDIM / 128, NTOK / 128), 256, GEMM_SMEM>>>(
            ph, HID, pwq + (size_t)l * QKVDIM * HID, HID,
            qkv_b + (size_t)l * QKVDIM, nullptr, pqkv, QKVDIM, HID);
        flash_kernel<<<dim3(SEQ / 64, BATCH * NHEAD), 128, FLASH_SMEM>>>(pqkv, alibi, pctx);
        mm_gemm<2><<<dim3(HID / 128, NTOK / 128), 256, GEMM_SMEM>>>(
            pctx, HID, pwd + (size_t)l * HID * HID, HID,
            dense_b + (size_t)l * HID, x, x, HID, HID);
        // --- MLP ---
        ln_kernel<<<NTOK, 256>>>(x, ln2w + l * HID, ln2b + l * HID, ph);
        mm_gemm<1><<<dim3(FFDIM / 128, NTOK / 128), 256, GEMM_SMEM>>>(
            ph, HID, pw1 + (size_t)l * FFDIM * HID, HID,
            b1 + (size_t)l * FFDIM, nullptr, pff, FFDIM, HID);
        mm_gemm<2><<<dim3(HID / 128, NTOK / 128), 256, GEMM_SMEM>>>(
            pff, FFDIM, pw2 + (size_t)l * HID * FFDIM, FFDIM,
            b2 + (size_t)l * HID, x, x, HID, FFDIM);
    }
}